// round 14
// baseline (speedup 1.0000x reference)
#include <cuda_runtime.h>
#include <cuda_bf16.h>
#include <cstdint>

#define Bsz 16384
#define Hd  1024
#define ODIM 128
#define RTOT (Bsz * 4)

// ---- scratch (static __device__ — no allocations allowed) ----
__device__ __nv_bfloat16 g_zh[(size_t)RTOT * Hd];   // z hi
__device__ __nv_bfloat16 g_zl[(size_t)RTOT * Hd];   // z lo
__device__ __nv_bfloat16 g_Mth[(size_t)Hd * Hd];    // (WqWk^T)^T = Wk Wq^T, hi
__device__ __nv_bfloat16 g_Mtl[(size_t)Hd * Hd];    // lo
__device__ __nv_bfloat16 g_Wvth[(size_t)Hd * Hd];   // Wv^T hi
__device__ __nv_bfloat16 g_Wvtl[(size_t)Hd * Hd];   // Wv^T lo
__device__ float g_vk[Hd];                          // Wk @ bq
__device__ float g_u[(size_t)RTOT * Hd];            // z @ M  (fp32)
__device__ __nv_bfloat16 g_yh[(size_t)Bsz * Hd];    // y hi
__device__ __nv_bfloat16 g_yl[(size_t)Bsz * Hd];    // y lo

// ============================================================
// helpers
// ============================================================
__device__ __forceinline__ uint32_t smem_u32(const void* p) {
    uint32_t a;
    asm("{ .reg .u64 t; cvta.to.shared.u64 t, %1; cvt.u32.u64 %0, t; }" : "=r"(a) : "l"(p));
    return a;
}
__device__ __forceinline__ void ldsm4(uint32_t (&r)[4], uint32_t addr) {
    asm volatile("ldmatrix.sync.aligned.m8n8.x4.shared.b16 {%0,%1,%2,%3}, [%4];"
                 : "=r"(r[0]), "=r"(r[1]), "=r"(r[2]), "=r"(r[3]) : "r"(addr));
}
__device__ __forceinline__ void mma16816(float (&d)[4], const uint32_t (&a)[4],
                                         uint32_t b0, uint32_t b1) {
    asm volatile(
        "mma.sync.aligned.m16n8k16.row.col.f32.bf16.bf16.f32 "
        "{%0,%1,%2,%3}, {%4,%5,%6,%7}, {%8,%9}, {%0,%1,%2,%3};"
        : "+f"(d[0]), "+f"(d[1]), "+f"(d[2]), "+f"(d[3])
        : "r"(a[0]), "r"(a[1]), "r"(a[2]), "r"(a[3]), "r"(b0), "r"(b1));
}
__device__ __forceinline__ const float* fsel(const float* f1, const float* f2,
                                             const float* f3, const float* f4, int t) {
    return t == 0 ? f1 : t == 1 ? f2 : t == 2 ? f3 : f4;
}
__device__ __forceinline__ void split_bf16(float v, __nv_bfloat16& h, __nv_bfloat16& l) {
    h = __float2bfloat16(v);
    l = __float2bfloat16(v - __bfloat162float(h));
}

// ============================================================
// prep_z: f1..f4 -> g_zh/g_zl, row r = b*4+t
// ============================================================
__global__ __launch_bounds__(256) void prep_z_kernel(const float* __restrict__ f1,
                                                     const float* __restrict__ f2,
                                                     const float* __restrict__ f3,
                                                     const float* __restrict__ f4) {
    size_t gid = (size_t)blockIdx.x * 256 + threadIdx.x;   // over RTOT * (Hd/4)
    int r = (int)(gid >> 8);
    int jj = (int)(gid & 255);
    const float* src = fsel(f1, f2, f3, f4, r & 3) + (size_t)(r >> 2) * Hd;
    float4 v = ((const float4*)src)[jj];
    __nv_bfloat16 hx, lx, hy, ly, hz, lz, hw, lw;
    split_bf16(v.x, hx, lx); split_bf16(v.y, hy, ly);
    split_bf16(v.z, hz, lz); split_bf16(v.w, hw, lw);
    __nv_bfloat162* dh = (__nv_bfloat162*)(g_zh + (size_t)r * Hd + jj * 4);
    __nv_bfloat162* dl = (__nv_bfloat162*)(g_zl + (size_t)r * Hd + jj * 4);
    dh[0] = __halves2bfloat162(hx, hy); dh[1] = __halves2bfloat162(hz, hw);
    dl[0] = __halves2bfloat162(lx, ly); dl[1] = __halves2bfloat162(lz, lw);
}

// ============================================================
// Mt = Wk @ Wq^T -> bf16 hi/lo (SIMT fp32 GEMM, small: 1024^3)
// ============================================================
#define BM 128
#define BN 128
#define BK 8
#define TM 8
#define TN 8
__global__ __launch_bounds__(256) void mt_gemm_kernel(const float* __restrict__ Wk,
                                                      const float* __restrict__ Wq) {
    __shared__ float As[BK][BM];
    __shared__ float Bs[BK][BN];
    const int tid = threadIdx.x;
    const int brow = blockIdx.y * BM;
    const int bcol = blockIdx.x * BN;
    const int lrow = tid >> 1, lcol = (tid & 1) * 4;
    const float* aptr = Wk + (size_t)(brow + lrow) * Hd + lcol;
    const float* bptr = Wq + (size_t)(bcol + lrow) * Hd + lcol;
    const int trow = (tid >> 4) * TM, tcol = (tid & 15) * TN;
    float acc[TM][TN] = {};
    for (int k0 = 0; k0 < Hd; k0 += BK) {
        float4 av = *(const float4*)(aptr + k0);
        As[lcol + 0][lrow] = av.x; As[lcol + 1][lrow] = av.y;
        As[lcol + 2][lrow] = av.z; As[lcol + 3][lrow] = av.w;
        float4 bv4 = *(const float4*)(bptr + k0);
        Bs[lcol + 0][lrow] = bv4.x; Bs[lcol + 1][lrow] = bv4.y;
        Bs[lcol + 2][lrow] = bv4.z; Bs[lcol + 3][lrow] = bv4.w;
        __syncthreads();
#pragma unroll
        for (int kk = 0; kk < BK; kk++) {
            float a[TM], b[TN];
            *(float4*)&a[0] = *(const float4*)&As[kk][trow];
            *(float4*)&a[4] = *(const float4*)&As[kk][trow + 4];
            *(float4*)&b[0] = *(const float4*)&Bs[kk][tcol];
            *(float4*)&b[4] = *(const float4*)&Bs[kk][tcol + 4];
#pragma unroll
            for (int i = 0; i < TM; i++)
#pragma unroll
                for (int j = 0; j < TN; j++) acc[i][j] += a[i] * b[j];
        }
        __syncthreads();
    }
#pragma unroll
    for (int i = 0; i < TM; i++) {
        size_t off = (size_t)(brow + trow + i) * Hd + bcol + tcol;
#pragma unroll
        for (int j = 0; j < TN; j += 2) {
            __nv_bfloat16 h0, l0, h1, l1;
            split_bf16(acc[i][j], h0, l0);
            split_bf16(acc[i][j + 1], h1, l1);
            *(__nv_bfloat162*)(g_Mth + off + j) = __halves2bfloat162(h0, h1);
            *(__nv_bfloat162*)(g_Mtl + off + j) = __halves2bfloat162(l0, l1);
        }
    }
}

// ============================================================
// Wvt[n][k] = Wv[k][n] -> bf16 hi/lo
// ============================================================
__global__ __launch_bounds__(256) void wvt_kernel(const float* __restrict__ Wv) {
    __shared__ float tile[32][33];
    const int tx = threadIdx.x & 31, ty8 = threadIdx.x >> 5;  // 32x8
    const int n0 = blockIdx.x * 32, k0 = blockIdx.y * 32;
#pragma unroll
    for (int r = 0; r < 4; r++) {
        int ky = ty8 + r * 8;
        tile[ky][tx] = Wv[(size_t)(k0 + ky) * Hd + n0 + tx];
    }
    __syncthreads();
#pragma unroll
    for (int r = 0; r < 4; r++) {
        int ny = ty8 + r * 8;
        float v = tile[tx][ny];
        __nv_bfloat16 h, l;
        split_bf16(v, h, l);
        g_Wvth[(size_t)(n0 + ny) * Hd + k0 + tx] = h;
        g_Wvtl[(size_t)(n0 + ny) * Hd + k0 + tx] = l;
    }
}

// ============================================================
// vk = Wk @ bq
// ============================================================
__global__ __launch_bounds__(256) void vk_kernel(const float* __restrict__ Wk,
                                                 const float* __restrict__ bq) {
    int warp = threadIdx.x >> 5, lane = threadIdx.x & 31;
    int row = blockIdx.x * 8 + warp;
    float s = 0.f;
    for (int m = lane; m < Hd; m += 32) s += Wk[(size_t)row * Hd + m] * bq[m];
#pragma unroll
    for (int off = 16; off; off >>= 1) s += __shfl_xor_sync(0xffffffffu, s, off);
    if (lane == 0) g_vk[row] = s;
}

// ============================================================
// HMMA bf16x3 GEMM body (pointers bound IN DEVICE CODE).
//   C[rows,1024] = A@B^T (+ biasScale*bias)
//   CTA tile 128x128 (R11-proven reuse), Kc=16, 8 warps (2m x 4n), warp 64x32.
//   Double-buffered static SMEM 48KB. Fragment loads via ldmatrix.x4
//   (12 LDSM/warp/chunk vs 48 LDS.32). Pass-major MMA order.
// ============================================================
#define HK 16
#define HLD 24    // row stride in bf16 (48B): LDSM rows hit banks 12r%32 — disjoint
#define SM_STG (4 * 128 * HLD * 2)   // 24576 B per stage
#define SM_BUF (128 * HLD * 2)       // 6144 B per buffer
#define SM_MF  (16 * HLD * 2)        // 768 B per 16-row block
template <bool BIAS>
__device__ __forceinline__ void hmma_gemm_body(
    const __nv_bfloat16* __restrict__ Ah, const __nv_bfloat16* __restrict__ Al,
    const __nv_bfloat16* __restrict__ Bh, const __nv_bfloat16* __restrict__ Bl,
    float* __restrict__ C, const float* __restrict__ bias, float biasScale) {
    __shared__ __nv_bfloat16 sm[2][4][128][HLD];   // [stage][buf][row][col] 48KB

    const int tid = threadIdx.x;
    const int wid = tid >> 5, lane = tid & 31;
    const int warp_m = wid & 1, warp_n = wid >> 1;  // 2m x 4n, warp tile 64x32
    const int g = lane >> 2, tg = lane & 3;
    const int row0 = blockIdx.y * 128, n0 = blockIdx.x * 128;
    const uint32_t sbase = smem_u32(sm);

    const __nv_bfloat16* ptr[4] = {Ah + (size_t)row0 * Hd, Al + (size_t)row0 * Hd,
                                   Bh + (size_t)n0 * Hd,  Bl + (size_t)n0 * Hd};

    // loader: per stage 4 bufs x 128 rows x 2 granules(16B); 4/thread
    const int lrow = tid >> 1, lq = tid & 1;
    const size_t goff = (size_t)lrow * Hd + lq * 8;

    uint4 p[4];
    auto ldg_chunk = [&](int c) {
        const size_t o = goff + (size_t)c * HK;
#pragma unroll
        for (int b = 0; b < 4; b++) p[b] = *(const uint4*)(ptr[b] + o);
    };
    auto sts_chunk = [&](int s) {
#pragma unroll
        for (int b = 0; b < 4; b++) *(uint4*)&sm[s][b][lrow][lq * 8] = p[b];
    };

    // ldmatrix per-lane address offsets (bytes), from the PTX fragment spec:
    // A x4 (16x16 tile): lanes 0-15 -> rows R+(lane&15), k-cols 0-7;
    //                    lanes 16-31 -> same rows, k-cols 8-15.
    const uint32_t a_off = (uint32_t)(((warp_m * 64 + (lane & 15)) * HLD + (lane >> 4) * 8) * 2);
    // B x4 (two n8-blocks x two k-halves): lanes 0-7 rows N..N+7 k0-7; 8-15 same rows k8-15;
    //                                      16-23 rows N+8..15 k0-7; 24-31 those rows k8-15.
    const uint32_t b_off = (uint32_t)(((warp_n * 32 + ((lane >> 4) & 1) * 8 + (lane & 7)) * HLD +
                                      ((lane >> 3) & 1) * 8) * 2);

    float acc[4][4][4] = {};   // [mf][nf][reg]

    ldg_chunk(0);
    sts_chunk(0);
    __syncthreads();

    for (int c = 0; c < Hd / HK; c++) {
        const int s = c & 1;
        if (c < Hd / HK - 1) ldg_chunk(c + 1);

        const uint32_t sb = sbase + s * SM_STG;
        uint32_t ah[4][4], al[4][4], bh4[2][4], bl4[2][4];
#pragma unroll
        for (int mf = 0; mf < 4; mf++) {
            ldsm4(ah[mf], sb + 0 * SM_BUF + a_off + mf * SM_MF);
            ldsm4(al[mf], sb + 1 * SM_BUF + a_off + mf * SM_MF);
        }
#pragma unroll
        for (int pr = 0; pr < 2; pr++) {
            ldsm4(bh4[pr], sb + 2 * SM_BUF + b_off + pr * SM_MF);
            ldsm4(bl4[pr], sb + 3 * SM_BUF + b_off + pr * SM_MF);
        }
        // pass-major: consecutive MMAs hit different accumulators
#pragma unroll
        for (int mf = 0; mf < 4; mf++)
#pragma unroll
            for (int nf = 0; nf < 4; nf++)
                mma16816(acc[mf][nf], ah[mf], bh4[nf >> 1][(nf & 1) * 2],
                         bh4[nf >> 1][(nf & 1) * 2 + 1]);
#pragma unroll
        for (int mf = 0; mf < 4; mf++)
#pragma unroll
            for (int nf = 0; nf < 4; nf++)
                mma16816(acc[mf][nf], al[mf], bh4[nf >> 1][(nf & 1) * 2],
                         bh4[nf >> 1][(nf & 1) * 2 + 1]);
#pragma unroll
        for (int mf = 0; mf < 4; mf++)
#pragma unroll
            for (int nf = 0; nf < 4; nf++)
                mma16816(acc[mf][nf], ah[mf], bl4[nf >> 1][(nf & 1) * 2],
                         bl4[nf >> 1][(nf & 1) * 2 + 1]);

        if (c < Hd / HK - 1) sts_chunk(s ^ 1);
        __syncthreads();
    }

    // epilogue (R9-proven): c0,c1 = row g cols 2tg..; c2,c3 = row g+8
#pragma unroll
    for (int mf = 0; mf < 4; mf++) {
        const int rg = row0 + warp_m * 64 + mf * 16 + g;
#pragma unroll
        for (int nf = 0; nf < 4; nf++) {
            const int cg = n0 + warp_n * 32 + nf * 8 + tg * 2;
            float2 v0 = make_float2(acc[mf][nf][0], acc[mf][nf][1]);
            float2 v1 = make_float2(acc[mf][nf][2], acc[mf][nf][3]);
            if (BIAS) {
                float b0 = biasScale * bias[cg], b1 = biasScale * bias[cg + 1];
                v0.x += b0; v0.y += b1; v1.x += b0; v1.y += b1;
            }
            *(float2*)(C + (size_t)rg * Hd + cg) = v0;
            *(float2*)(C + (size_t)(rg + 8) * Hd + cg) = v1;
        }
    }
}

// u = z @ M : all operands are __device__ globals, bound in device code
__global__ __launch_bounds__(256) void u_hmma_kernel() {
    hmma_gemm_body<false>(g_zh, g_zl, g_Mth, g_Mtl, g_u, nullptr, 0.f);
}
// x = y @ Wv^T + 4*bv : globals bound in device code; bv/xout are harness ptrs
__global__ __launch_bounds__(256) void x_hmma_kernel(const float* __restrict__ bv,
                                                     float* __restrict__ xout) {
    hmma_gemm_body<true>(g_yh, g_yl, g_Wvth, g_Wvtl, xout, bv, 4.f);
}

// ============================================================
// per-batch attention, register-resident (R12-proven):
// thread owns 8 contiguous j; logits via u,z; softmax; y bf16 split
// ============================================================
__global__ __launch_bounds__(128) void attn_kernel(const float* __restrict__ f1,
                                                   const float* __restrict__ f2,
                                                   const float* __restrict__ f3,
                                                   const float* __restrict__ f4) {
    const int b = blockIdx.x, tid = threadIdx.x;
    const int jb = tid * 8;

    float z[4][8], u[4][8];
#pragma unroll
    for (int t = 0; t < 4; t++) {
        const float4* zp = (const float4*)(fsel(f1, f2, f3, f4, t) + (size_t)b * Hd + jb);
        const float4* up = (const float4*)(g_u + ((size_t)b * 4 + t) * Hd + jb);
        *(float4*)&z[t][0] = zp[0]; *(float4*)&z[t][4] = zp[1];
        *(float4*)&u[t][0] = up[0]; *(float4*)&u[t][4] = up[1];
    }
    float vk8[8];
    *(float4*)&vk8[0] = *(const float4*)(g_vk + jb);
    *(float4*)&vk8[4] = *(const float4*)(g_vk + jb + 4);

    float aG[16] = {}, aC[4] = {};
#pragma unroll
    for (int j = 0; j < 8; j++) {
#pragma unroll
        for (int t = 0; t < 4; t++)
#pragma unroll
            for (int s = 0; s < 4; s++) aG[t * 4 + s] += u[t][j] * z[s][j];
#pragma unroll
        for (int s = 0; s < 4; s++) aC[s] += z[s][j] * vk8[j];
    }
#pragma unroll
    for (int a = 0; a < 16; a++)
#pragma unroll
        for (int off = 16; off; off >>= 1) aG[a] += __shfl_xor_sync(0xffffffffu, aG[a], off);
#pragma unroll
    for (int a = 0; a < 4; a++)
#pragma unroll
        for (int off = 16; off; off >>= 1) aC[a] += __shfl_xor_sync(0xffffffffu, aC[a], off);

    __shared__ float rbuf[4][20];
    __shared__ float sw[4];
    const int warp = tid >> 5, lane = tid & 31;
    if (lane == 0) {
#pragma unroll
        for (int a = 0; a < 16; a++) rbuf[warp][a] = aG[a];
#pragma unroll
        for (int a = 0; a < 4; a++) rbuf[warp][16 + a] = aC[a];
    }
    __syncthreads();
    if (tid == 0) {
        float L[20];
#pragma unroll
        for (int a = 0; a < 20; a++) L[a] = rbuf[0][a] + rbuf[1][a] + rbuf[2][a] + rbuf[3][a];
        float w[4] = {0.f, 0.f, 0.f, 0.f};
#pragma unroll
        for (int t = 0; t < 4; t++) {
            float l0 = L[t * 4 + 0] + L[16];
            float l1 = L[t * 4 + 1] + L[17];
            float l2 = L[t * 4 + 2] + L[18];
            float l3 = L[t * 4 + 3] + L[19];
            float m = fmaxf(fmaxf(l0, l1), fmaxf(l2, l3));
            float e0 = expf(l0 - m), e1 = expf(l1 - m), e2 = expf(l2 - m), e3 = expf(l3 - m);
            float inv = 1.f / (e0 + e1 + e2 + e3);
            w[0] += e0 * inv; w[1] += e1 * inv; w[2] += e2 * inv; w[3] += e3 * inv;
        }
        sw[0] = w[0]; sw[1] = w[1]; sw[2] = w[2]; sw[3] = w[3];
    }
    __syncthreads();
    const float w0 = sw[0], w1 = sw[1], w2 = sw[2], w3 = sw[3];

    __nv_bfloat162 oh[4], ol[4];
#pragma unroll
    for (int jj = 0; jj < 4; jj++) {
        float o0 = w0 * z[0][jj * 2]     + w1 * z[1][jj * 2]     + w2 * z[2][jj * 2]     + w3 * z[3][jj * 2];
        float o1 = w0 * z[0][jj * 2 + 1] + w1 * z[1][jj * 2 + 1] + w2 * z[2][jj * 2 + 1] + w3 * z[3][jj * 2 + 1];
        __nv_bfloat16 h0, l0, h1, l1;
        split_bf16(o0, h0, l0); split_bf16(o1, h1, l1);
        oh[jj] = __halves2bfloat162(h0, h1);
        ol[jj] = __halves2bfloat162(l0, l1);
    }
    *(uint2*)(g_yh + (size_t)b * Hd + jb)     = *(uint2*)&oh[0];
    *(uint2*)(g_yh + (size_t)b * Hd + jb + 4) = *(uint2*)&oh[2];
    *(uint2*)(g_yl + (size_t)b * Hd + jb)     = *(uint2*)&ol[0];
    *(uint2*)(g_yl + (size_t)b * Hd + jb + 4) = *(uint2*)&ol[2];
}

// ============================================================
// out = softmax(x @ Wfc + bfc)
// ============================================================
__global__ __launch_bounds__(128) void fc_kernel(const float* __restrict__ x,
                                                 const float* __restrict__ Wfc,
                                                 const float* __restrict__ bfc,
                                                 float* __restrict__ oout) {
    __shared__ float sxT[Hd][8];
    const int tid = threadIdx.x;
    const int row0 = blockIdx.x * 8;
    for (int idx = tid; idx < 8 * Hd; idx += 128) {
        int r = idx >> 10;
        int k = idx & (Hd - 1);
        sxT[k][r] = x[(size_t)(row0 + r) * Hd + k];
    }
    __syncthreads();
    float acc[8] = {};
#pragma unroll 4
    for (int k = 0; k < Hd; k++) {
        float wv = Wfc[(size_t)k * ODIM + tid];
        float4 lo = *(const float4*)&sxT[k][0];
        float4 hi = *(const float4*)&sxT[k][4];
        acc[0] += lo.x * wv; acc[1] += lo.y * wv; acc[2] += lo.z * wv; acc[3] += lo.w * wv;
        acc[4] += hi.x * wv; acc[5] += hi.y * wv; acc[6] += hi.z * wv; acc[7] += hi.w * wv;
    }
    const float bb = bfc[tid];
#pragma unroll
    for (int r = 0; r < 8; r++) acc[r] += bb;

    __shared__ float slog[8][128];
#pragma unroll
    for (int r = 0; r < 8; r++) slog[r][tid] = acc[r];
    __syncthreads();
    __shared__ float smax[8], sinv[8];
    const int warp = tid >> 5, lane = tid & 31;
#pragma unroll
    for (int rr = 0; rr < 2; rr++) {
        int r = warp * 2 + rr;
        float v0 = slog[r][lane], v1 = slog[r][lane + 32];
        float v2 = slog[r][lane + 64], v3 = slog[r][lane + 96];
        float m = fmaxf(fmaxf(v0, v1), fmaxf(v2, v3));
#pragma unroll
        for (int off = 16; off; off >>= 1) m = fmaxf(m, __shfl_xor_sync(0xffffffffu, m, off));
        float s = expf(v0 - m) + expf(v1 - m) + expf(v2 - m) + expf(v3 - m);
#pragma unroll
        for (int off = 16; off; off >>= 1) s += __shfl_xor_sync(0xffffffffu, s, off);
        if (lane == 0) { smax[r] = m; sinv[r] = 1.f / s; }
    }
    __syncthreads();
#pragma unroll
    for (int r = 0; r < 8; r++)
        oout[(size_t)(row0 + r) * ODIM + tid] = expf(acc[r] - smax[r]) * sinv[r];
}

// ============================================================
extern "C" void kernel_launch(void* const* d_in, const int* in_sizes, int n_in,
                              void* d_out, int out_size) {
    (void)in_sizes; (void)n_in; (void)out_size;
    const float* f1  = (const float*)d_in[0];
    const float* f2  = (const float*)d_in[1];
    const float* f3  = (const float*)d_in[2];
    const float* f4  = (const float*)d_in[3];
    const float* Wq  = (const float*)d_in[4];
    const float* bq  = (const float*)d_in[5];
    const float* Wk  = (const float*)d_in[6];
    // d_in[7] = bk: cancels inside softmax — unused
    const float* Wv  = (const float*)d_in[8];
    const float* bv  = (const float*)d_in[9];
    const float* Wfc = (const float*)d_in[10];
    const float* bfc = (const float*)d_in[11];

    float* xout = (float*)d_out;                 // [B, H]
    float* oout = xout + (size_t)Bsz * Hd;       // [B, OUT]

    // bf16 split conversions + small precomputes
    prep_z_kernel<<<(RTOT * (Hd / 4)) / 256, 256>>>(f1, f2, f3, f4);
    mt_gemm_kernel<<<dim3(Hd / BN, Hd / BM), 256>>>(Wk, Wq);
    wvt_kernel<<<dim3(Hd / 32, Hd / 32), 256>>>(Wv);

    // u = z @ M  (HMMA bf16x3, 128x128, ldmatrix frags) — 4th launch: ncu profiles this
    u_hmma_kernel<<<dim3(Hd / 128, RTOT / 128), 256>>>();

    // vk needed only by attn — launch after u so u sits at capture position
    vk_kernel<<<Hd / 8, 256>>>(Wk, bq);

    // attention reduce -> y (bf16 split, register-resident)
    attn_kernel<<<Bsz, 128>>>(f1, f2, f3, f4);

    // x = y @ Wv + 4*bv  (HMMA bf16x3)
    x_hmma_kernel<<<dim3(Hd / 128, Bsz / 128), 256>>>(bv, xout);

    // out = softmax(x @ Wfc + bfc)
    fc_kernel<<<Bsz / 8, 128>>>(xout, Wfc, bfc, oout);
}

// round 15
// speedup vs baseline: 1.2347x; 1.2347x over previous
#include <cuda_runtime.h>
#include <cuda_bf16.h>
#include <cstdint>

#define Bsz 16384
#define Hd  1024
#define ODIM 128
#define RTOT (Bsz * 4)

// ---- scratch (static __device__ — no allocations allowed) ----
__device__ __nv_bfloat16 g_zh[(size_t)RTOT * Hd];   // z hi
__device__ __nv_bfloat16 g_zl[(size_t)RTOT * Hd];   // z lo
__device__ __nv_bfloat16 g_Mth[(size_t)Hd * Hd];    // (WqWk^T)^T = Wk Wq^T, hi
__device__ __nv_bfloat16 g_Mtl[(size_t)Hd * Hd];    // lo
__device__ __nv_bfloat16 g_Wvth[(size_t)Hd * Hd];   // Wv^T hi
__device__ __nv_bfloat16 g_Wvtl[(size_t)Hd * Hd];   // Wv^T lo
__device__ float g_vk[Hd];                          // Wk @ bq
__device__ float g_u[(size_t)RTOT * Hd];            // z @ M  (fp32)
__device__ __nv_bfloat16 g_yh[(size_t)Bsz * Hd];    // y hi
__device__ __nv_bfloat16 g_yl[(size_t)Bsz * Hd];    // y lo

// ============================================================
// helpers
// ============================================================
__device__ __forceinline__ void mma16816(float (&d)[4], const uint32_t (&a)[4],
                                         uint32_t b0, uint32_t b1) {
    asm volatile(
        "mma.sync.aligned.m16n8k16.row.col.f32.bf16.bf16.f32 "
        "{%0,%1,%2,%3}, {%4,%5,%6,%7}, {%8,%9}, {%0,%1,%2,%3};"
        : "+f"(d[0]), "+f"(d[1]), "+f"(d[2]), "+f"(d[3])
        : "r"(a[0]), "r"(a[1]), "r"(a[2]), "r"(a[3]), "r"(b0), "r"(b1));
}
__device__ __forceinline__ const float* fsel(const float* f1, const float* f2,
                                             const float* f3, const float* f4, int t) {
    return t == 0 ? f1 : t == 1 ? f2 : t == 2 ? f3 : f4;
}
__device__ __forceinline__ void split_bf16(float v, __nv_bfloat16& h, __nv_bfloat16& l) {
    h = __float2bfloat16(v);
    l = __float2bfloat16(v - __bfloat162float(h));
}

// ============================================================
// prep_z: f1..f4 -> g_zh/g_zl, row r = b*4+t
// ============================================================
__global__ __launch_bounds__(256) void prep_z_kernel(const float* __restrict__ f1,
                                                     const float* __restrict__ f2,
                                                     const float* __restrict__ f3,
                                                     const float* __restrict__ f4) {
    size_t gid = (size_t)blockIdx.x * 256 + threadIdx.x;   // over RTOT * (Hd/4)
    int r = (int)(gid >> 8);
    int jj = (int)(gid & 255);
    const float* src = fsel(f1, f2, f3, f4, r & 3) + (size_t)(r >> 2) * Hd;
    float4 v = ((const float4*)src)[jj];
    __nv_bfloat16 hx, lx, hy, ly, hz, lz, hw, lw;
    split_bf16(v.x, hx, lx); split_bf16(v.y, hy, ly);
    split_bf16(v.z, hz, lz); split_bf16(v.w, hw, lw);
    __nv_bfloat162* dh = (__nv_bfloat162*)(g_zh + (size_t)r * Hd + jj * 4);
    __nv_bfloat162* dl = (__nv_bfloat162*)(g_zl + (size_t)r * Hd + jj * 4);
    dh[0] = __halves2bfloat162(hx, hy); dh[1] = __halves2bfloat162(hz, hw);
    dl[0] = __halves2bfloat162(lx, ly); dl[1] = __halves2bfloat162(lz, lw);
}

// ============================================================
// Mt = Wk @ Wq^T -> bf16 hi/lo (SIMT fp32 GEMM, small: 1024^3)
// ============================================================
#define BM 128
#define BN 128
#define BK 8
#define TM 8
#define TN 8
__global__ __launch_bounds__(256) void mt_gemm_kernel(const float* __restrict__ Wk,
                                                      const float* __restrict__ Wq) {
    __shared__ float As[BK][BM];
    __shared__ float Bs[BK][BN];
    const int tid = threadIdx.x;
    const int brow = blockIdx.y * BM;
    const int bcol = blockIdx.x * BN;
    const int lrow = tid >> 1, lcol = (tid & 1) * 4;
    const float* aptr = Wk + (size_t)(brow + lrow) * Hd + lcol;
    const float* bptr = Wq + (size_t)(bcol + lrow) * Hd + lcol;
    const int trow = (tid >> 4) * TM, tcol = (tid & 15) * TN;
    float acc[TM][TN] = {};
    for (int k0 = 0; k0 < Hd; k0 += BK) {
        float4 av = *(const float4*)(aptr + k0);
        As[lcol + 0][lrow] = av.x; As[lcol + 1][lrow] = av.y;
        As[lcol + 2][lrow] = av.z; As[lcol + 3][lrow] = av.w;
        float4 bv4 = *(const float4*)(bptr + k0);
        Bs[lcol + 0][lrow] = bv4.x; Bs[lcol + 1][lrow] = bv4.y;
        Bs[lcol + 2][lrow] = bv4.z; Bs[lcol + 3][lrow] = bv4.w;
        __syncthreads();
#pragma unroll
        for (int kk = 0; kk < BK; kk++) {
            float a[TM], b[TN];
            *(float4*)&a[0] = *(const float4*)&As[kk][trow];
            *(float4*)&a[4] = *(const float4*)&As[kk][trow + 4];
            *(float4*)&b[0] = *(const float4*)&Bs[kk][tcol];
            *(float4*)&b[4] = *(const float4*)&Bs[kk][tcol + 4];
#pragma unroll
            for (int i = 0; i < TM; i++)
#pragma unroll
                for (int j = 0; j < TN; j++) acc[i][j] += a[i] * b[j];
        }
        __syncthreads();
    }
#pragma unroll
    for (int i = 0; i < TM; i++) {
        size_t off = (size_t)(brow + trow + i) * Hd + bcol + tcol;
#pragma unroll
        for (int j = 0; j < TN; j += 2) {
            __nv_bfloat16 h0, l0, h1, l1;
            split_bf16(acc[i][j], h0, l0);
            split_bf16(acc[i][j + 1], h1, l1);
            *(__nv_bfloat162*)(g_Mth + off + j) = __halves2bfloat162(h0, h1);
            *(__nv_bfloat162*)(g_Mtl + off + j) = __halves2bfloat162(l0, l1);
        }
    }
}

// ============================================================
// Wvt[n][k] = Wv[k][n] -> bf16 hi/lo
// ============================================================
__global__ __launch_bounds__(256) void wvt_kernel(const float* __restrict__ Wv) {
    __shared__ float tile[32][33];
    const int tx = threadIdx.x & 31, ty8 = threadIdx.x >> 5;  // 32x8
    const int n0 = blockIdx.x * 32, k0 = blockIdx.y * 32;
#pragma unroll
    for (int r = 0; r < 4; r++) {
        int ky = ty8 + r * 8;
        tile[ky][tx] = Wv[(size_t)(k0 + ky) * Hd + n0 + tx];
    }
    __syncthreads();
#pragma unroll
    for (int r = 0; r < 4; r++) {
        int ny = ty8 + r * 8;
        float v = tile[tx][ny];
        __nv_bfloat16 h, l;
        split_bf16(v, h, l);
        g_Wvth[(size_t)(n0 + ny) * Hd + k0 + tx] = h;
        g_Wvtl[(size_t)(n0 + ny) * Hd + k0 + tx] = l;
    }
}

// ============================================================
// vk = Wk @ bq
// ============================================================
__global__ __launch_bounds__(256) void vk_kernel(const float* __restrict__ Wk,
                                                 const float* __restrict__ bq) {
    int warp = threadIdx.x >> 5, lane = threadIdx.x & 31;
    int row = blockIdx.x * 8 + warp;
    float s = 0.f;
    for (int m = lane; m < Hd; m += 32) s += Wk[(size_t)row * Hd + m] * bq[m];
#pragma unroll
    for (int off = 16; off; off >>= 1) s += __shfl_xor_sync(0xffffffffu, s, off);
    if (lane == 0) g_vk[row] = s;
}

// ============================================================
// HMMA bf16x3 GEMM body (pointers bound IN DEVICE CODE).
//   C[rows,1024] = A@B^T (+ biasScale*bias)
//   CTA tile 128x128, Kc=16, 512 threads, 16 warps (4m x 4n), warp tile 32x32.
//   Double-buffered static SMEM 48KB. LDS.32 fragment loads (R9-proven).
//   Pass-major MMA order. 16 warps/SM = 4/SMSP to cover HMMA+LDS latency.
// ============================================================
#define HK 16
#define HLD 24    // row stride in bf16 (48B): conflict-free fragment LDS
template <bool BIAS>
__device__ __forceinline__ void hmma_gemm_body(
    const __nv_bfloat16* __restrict__ Ah, const __nv_bfloat16* __restrict__ Al,
    const __nv_bfloat16* __restrict__ Bh, const __nv_bfloat16* __restrict__ Bl,
    float* __restrict__ C, const float* __restrict__ bias, float biasScale) {
    __shared__ __nv_bfloat16 sm[2][4][128][HLD];   // [stage][buf][row][col] 48KB

    const int tid = threadIdx.x;
    const int wid = tid >> 5, lane = tid & 31;
    const int warp_m = wid & 3, warp_n = wid >> 2;  // 4m x 4n, warp tile 32x32
    const int g = lane >> 2, tg = lane & 3;
    const int row0 = blockIdx.y * 128, n0 = blockIdx.x * 128;

    const __nv_bfloat16* ptr[4] = {Ah + (size_t)row0 * Hd, Al + (size_t)row0 * Hd,
                                   Bh + (size_t)n0 * Hd,  Bl + (size_t)n0 * Hd};

    // loader: per stage 4 bufs x 128 rows x 2 granules(16B) = 1024 granules;
    // 512 threads -> 2 granules/thread (one in each of 2 buffers)
    const int half = tid >> 8;                 // 0: bufs 0,1  1: bufs 2,3
    const int lrow = (tid & 255) >> 1, lq = tid & 1;
    const size_t goff = (size_t)lrow * Hd + lq * 8;
    const int b0 = half * 2, b1 = half * 2 + 1;

    uint4 p0, p1;
    auto ldg_chunk = [&](int c) {
        const size_t o = goff + (size_t)c * HK;
        p0 = *(const uint4*)(ptr[b0] + o);
        p1 = *(const uint4*)(ptr[b1] + o);
    };
    auto sts_chunk = [&](int s) {
        *(uint4*)&sm[s][b0][lrow][lq * 8] = p0;
        *(uint4*)&sm[s][b1][lrow][lq * 8] = p1;
    };

    const int arow = warp_m * 32 + g;
    const int brow = warp_n * 32 + g;
    const int kc = 2 * tg;
    float acc[2][4][4] = {};   // [mf][nf][reg]

    ldg_chunk(0);
    sts_chunk(0);
    __syncthreads();

    for (int c = 0; c < Hd / HK; c++) {
        const int s = c & 1;
        if (c < Hd / HK - 1) ldg_chunk(c + 1);

        uint32_t ah[2][4], al[2][4], bh[4][2], bl[4][2];
#pragma unroll
        for (int mf = 0; mf < 2; mf++) {
            const int r = arow + mf * 16;
            ah[mf][0] = *(const uint32_t*)&sm[s][0][r][kc];
            ah[mf][1] = *(const uint32_t*)&sm[s][0][r + 8][kc];
            ah[mf][2] = *(const uint32_t*)&sm[s][0][r][kc + 8];
            ah[mf][3] = *(const uint32_t*)&sm[s][0][r + 8][kc + 8];
            al[mf][0] = *(const uint32_t*)&sm[s][1][r][kc];
            al[mf][1] = *(const uint32_t*)&sm[s][1][r + 8][kc];
            al[mf][2] = *(const uint32_t*)&sm[s][1][r][kc + 8];
            al[mf][3] = *(const uint32_t*)&sm[s][1][r + 8][kc + 8];
        }
#pragma unroll
        for (int nf = 0; nf < 4; nf++) {
            const int r = brow + nf * 8;
            bh[nf][0] = *(const uint32_t*)&sm[s][2][r][kc];
            bh[nf][1] = *(const uint32_t*)&sm[s][2][r][kc + 8];
            bl[nf][0] = *(const uint32_t*)&sm[s][3][r][kc];
            bl[nf][1] = *(const uint32_t*)&sm[s][3][r][kc + 8];
        }
        // pass-major: consecutive MMAs hit different accumulators
#pragma unroll
        for (int mf = 0; mf < 2; mf++)
#pragma unroll
            for (int nf = 0; nf < 4; nf++)
                mma16816(acc[mf][nf], ah[mf], bh[nf][0], bh[nf][1]);
#pragma unroll
        for (int mf = 0; mf < 2; mf++)
#pragma unroll
            for (int nf = 0; nf < 4; nf++)
                mma16816(acc[mf][nf], al[mf], bh[nf][0], bh[nf][1]);
#pragma unroll
        for (int mf = 0; mf < 2; mf++)
#pragma unroll
            for (int nf = 0; nf < 4; nf++)
                mma16816(acc[mf][nf], ah[mf], bl[nf][0], bl[nf][1]);

        if (c < Hd / HK - 1) sts_chunk(s ^ 1);
        __syncthreads();
    }

    // epilogue (R9-proven): c0,c1 = row g cols 2tg..; c2,c3 = row g+8
#pragma unroll
    for (int mf = 0; mf < 2; mf++) {
        const int rg = row0 + warp_m * 32 + mf * 16 + g;
#pragma unroll
        for (int nf = 0; nf < 4; nf++) {
            const int cg = n0 + warp_n * 32 + nf * 8 + tg * 2;
            float2 v0 = make_float2(acc[mf][nf][0], acc[mf][nf][1]);
            float2 v1 = make_float2(acc[mf][nf][2], acc[mf][nf][3]);
            if (BIAS) {
                float b0v = biasScale * bias[cg], b1v = biasScale * bias[cg + 1];
                v0.x += b0v; v0.y += b1v; v1.x += b0v; v1.y += b1v;
            }
            *(float2*)(C + (size_t)rg * Hd + cg) = v0;
            *(float2*)(C + (size_t)(rg + 8) * Hd + cg) = v1;
        }
    }
}

// u = z @ M : all operands are __device__ globals, bound in device code
__global__ __launch_bounds__(512) void u_hmma_kernel() {
    hmma_gemm_body<false>(g_zh, g_zl, g_Mth, g_Mtl, g_u, nullptr, 0.f);
}
// x = y @ Wv^T + 4*bv : globals bound in device code; bv/xout are harness ptrs
__global__ __launch_bounds__(512) void x_hmma_kernel(const float* __restrict__ bv,
                                                     float* __restrict__ xout) {
    hmma_gemm_body<true>(g_yh, g_yl, g_Wvth, g_Wvtl, xout, bv, 4.f);
}

// ============================================================
// per-batch attention, register-resident (R12-proven):
// thread owns 8 contiguous j; logits via u,z; softmax; y bf16 split
// ============================================================
__global__ __launch_bounds__(128) void attn_kernel(const float* __restrict__ f1,
                                                   const float* __restrict__ f2,
                                                   const float* __restrict__ f3,
                                                   const float* __restrict__ f4) {
    const int b = blockIdx.x, tid = threadIdx.x;
    const int jb = tid * 8;

    float z[4][8], u[4][8];
#pragma unroll
    for (int t = 0; t < 4; t++) {
        const float4* zp = (const float4*)(fsel(f1, f2, f3, f4, t) + (size_t)b * Hd + jb);
        const float4* up = (const float4*)(g_u + ((size_t)b * 4 + t) * Hd + jb);
        *(float4*)&z[t][0] = zp[0]; *(float4*)&z[t][4] = zp[1];
        *(float4*)&u[t][0] = up[0]; *(float4*)&u[t][4] = up[1];
    }
    float vk8[8];
    *(float4*)&vk8[0] = *(const float4*)(g_vk + jb);
    *(float4*)&vk8[4] = *(const float4*)(g_vk + jb + 4);

    float aG[16] = {}, aC[4] = {};
#pragma unroll
    for (int j = 0; j < 8; j++) {
#pragma unroll
        for (int t = 0; t < 4; t++)
#pragma unroll
            for (int s = 0; s < 4; s++) aG[t * 4 + s] += u[t][j] * z[s][j];
#pragma unroll
        for (int s = 0; s < 4; s++) aC[s] += z[s][j] * vk8[j];
    }
#pragma unroll
    for (int a = 0; a < 16; a++)
#pragma unroll
        for (int off = 16; off; off >>= 1) aG[a] += __shfl_xor_sync(0xffffffffu, aG[a], off);
#pragma unroll
    for (int a = 0; a < 4; a++)
#pragma unroll
        for (int off = 16; off; off >>= 1) aC[a] += __shfl_xor_sync(0xffffffffu, aC[a], off);

    __shared__ float rbuf[4][20];
    __shared__ float sw[4];
    const int warp = tid >> 5, lane = tid & 31;
    if (lane == 0) {
#pragma unroll
        for (int a = 0; a < 16; a++) rbuf[warp][a] = aG[a];
#pragma unroll
        for (int a = 0; a < 4; a++) rbuf[warp][16 + a] = aC[a];
    }
    __syncthreads();
    if (tid == 0) {
        float L[20];
#pragma unroll
        for (int a = 0; a < 20; a++) L[a] = rbuf[0][a] + rbuf[1][a] + rbuf[2][a] + rbuf[3][a];
        float w[4] = {0.f, 0.f, 0.f, 0.f};
#pragma unroll
        for (int t = 0; t < 4; t++) {
            float l0 = L[t * 4 + 0] + L[16];
            float l1 = L[t * 4 + 1] + L[17];
            float l2 = L[t * 4 + 2] + L[18];
            float l3 = L[t * 4 + 3] + L[19];
            float m = fmaxf(fmaxf(l0, l1), fmaxf(l2, l3));
            float e0 = expf(l0 - m), e1 = expf(l1 - m), e2 = expf(l2 - m), e3 = expf(l3 - m);
            float inv = 1.f / (e0 + e1 + e2 + e3);
            w[0] += e0 * inv; w[1] += e1 * inv; w[2] += e2 * inv; w[3] += e3 * inv;
        }
        sw[0] = w[0]; sw[1] = w[1]; sw[2] = w[2]; sw[3] = w[3];
    }
    __syncthreads();
    const float w0 = sw[0], w1 = sw[1], w2 = sw[2], w3 = sw[3];

    __nv_bfloat162 oh[4], ol[4];
#pragma unroll
    for (int jj = 0; jj < 4; jj++) {
        float o0 = w0 * z[0][jj * 2]     + w1 * z[1][jj * 2]     + w2 * z[2][jj * 2]     + w3 * z[3][jj * 2];
        float o1 = w0 * z[0][jj * 2 + 1] + w1 * z[1][jj * 2 + 1] + w2 * z[2][jj * 2 + 1] + w3 * z[3][jj * 2 + 1];
        __nv_bfloat16 h0, l0, h1, l1;
        split_bf16(o0, h0, l0); split_bf16(o1, h1, l1);
        oh[jj] = __halves2bfloat162(h0, h1);
        ol[jj] = __halves2bfloat162(l0, l1);
    }
    *(uint2*)(g_yh + (size_t)b * Hd + jb)     = *(uint2*)&oh[0];
    *(uint2*)(g_yh + (size_t)b * Hd + jb + 4) = *(uint2*)&oh[2];
    *(uint2*)(g_yl + (size_t)b * Hd + jb)     = *(uint2*)&ol[0];
    *(uint2*)(g_yl + (size_t)b * Hd + jb + 4) = *(uint2*)&ol[2];
}

// ============================================================
// out = softmax(x @ Wfc + bfc)
// ============================================================
__global__ __launch_bounds__(128) void fc_kernel(const float* __restrict__ x,
                                                 const float* __restrict__ Wfc,
                                                 const float* __restrict__ bfc,
                                                 float* __restrict__ oout) {
    __shared__ float sxT[Hd][8];
    const int tid = threadIdx.x;
    const int row0 = blockIdx.x * 8;
    for (int idx = tid; idx < 8 * Hd; idx += 128) {
        int r = idx >> 10;
        int k = idx & (Hd - 1);
        sxT[k][r] = x[(size_t)(row0 + r) * Hd + k];
    }
    __syncthreads();
    float acc[8] = {};
#pragma unroll 4
    for (int k = 0; k < Hd; k++) {
        float wv = Wfc[(size_t)k * ODIM + tid];
        float4 lo = *(const float4*)&sxT[k][0];
        float4 hi = *(const float4*)&sxT[k][4];
        acc[0] += lo.x * wv; acc[1] += lo.y * wv; acc[2] += lo.z * wv; acc[3] += lo.w * wv;
        acc[4] += hi.x * wv; acc[5] += hi.y * wv; acc[6] += hi.z * wv; acc[7] += hi.w * wv;
    }
    const float bb = bfc[tid];
#pragma unroll
    for (int r = 0; r < 8; r++) acc[r] += bb;

    __shared__ float slog[8][128];
#pragma unroll
    for (int r = 0; r < 8; r++) slog[r][tid] = acc[r];
    __syncthreads();
    __shared__ float smax[8], sinv[8];
    const int warp = tid >> 5, lane = tid & 31;
#pragma unroll
    for (int rr = 0; rr < 2; rr++) {
        int r = warp * 2 + rr;
        float v0 = slog[r][lane], v1 = slog[r][lane + 32];
        float v2 = slog[r][lane + 64], v3 = slog[r][lane + 96];
        float m = fmaxf(fmaxf(v0, v1), fmaxf(v2, v3));
#pragma unroll
        for (int off = 16; off; off >>= 1) m = fmaxf(m, __shfl_xor_sync(0xffffffffu, m, off));
        float s = expf(v0 - m) + expf(v1 - m) + expf(v2 - m) + expf(v3 - m);
#pragma unroll
        for (int off = 16; off; off >>= 1) s += __shfl_xor_sync(0xffffffffu, s, off);
        if (lane == 0) { smax[r] = m; sinv[r] = 1.f / s; }
    }
    __syncthreads();
#pragma unroll
    for (int r = 0; r < 8; r++)
        oout[(size_t)(row0 + r) * ODIM + tid] = expf(acc[r] - smax[r]) * sinv[r];
}

// ============================================================
extern "C" void kernel_launch(void* const* d_in, const int* in_sizes, int n_in,
                              void* d_out, int out_size) {
    (void)in_sizes; (void)n_in; (void)out_size;
    const float* f1  = (const float*)d_in[0];
    const float* f2  = (const float*)d_in[1];
    const float* f3  = (const float*)d_in[2];
    const float* f4  = (const float*)d_in[3];
    const float* Wq  = (const float*)d_in[4];
    const float* bq  = (const float*)d_in[5];
    const float* Wk  = (const float*)d_in[6];
    // d_in[7] = bk: cancels inside softmax — unused
    const float* Wv  = (const float*)d_in[8];
    const float* bv  = (const float*)d_in[9];
    const float* Wfc = (const float*)d_in[10];
    const float* bfc = (const float*)d_in[11];

    float* xout = (float*)d_out;                 // [B, H]
    float* oout = xout + (size_t)Bsz * Hd;       // [B, OUT]

    // bf16 split conversions + small precomputes
    prep_z_kernel<<<(RTOT * (Hd / 4)) / 256, 256>>>(f1, f2, f3, f4);
    mt_gemm_kernel<<<dim3(Hd / BN, Hd / BM), 256>>>(Wk, Wq);
    wvt_kernel<<<dim3(Hd / 32, Hd / 32), 256>>>(Wv);

    // u = z @ M  (HMMA bf16x3, 128x128, 512 threads) — 4th launch: ncu profiles this
    u_hmma_kernel<<<dim3(Hd / 128, RTOT / 128), 512>>>();

    // vk needed only by attn
    vk_kernel<<<Hd / 8, 256>>>(Wk, bq);

    // attention reduce -> y (bf16 split, register-resident)
    attn_kernel<<<Bsz, 128>>>(f1, f2, f3, f4);

    // x = y @ Wv + 4*bv  (HMMA bf16x3)
    x_hmma_kernel<<<dim3(Hd / 128, Bsz / 128), 512>>>(bv, xout);

    // out = softmax(x @ Wfc + bfc)
    fc_kernel<<<Bsz / 8, 128>>>(xout, Wfc, bfc, oout);
}

// round 16
// speedup vs baseline: 1.5952x; 1.2919x over previous
#include <cuda_runtime.h>
#include <cuda_bf16.h>
#include <cstdint>

#define Bsz 16384
#define Hd  1024
#define ODIM 128
#define RTOT (Bsz * 4)

// ---- scratch (static __device__ — no allocations allowed) ----
__device__ __nv_bfloat16 g_zh[(size_t)RTOT * Hd];   // z hi
__device__ __nv_bfloat16 g_zl[(size_t)RTOT * Hd];   // z lo
__device__ __nv_bfloat16 g_Mth[(size_t)Hd * Hd];    // (WqWk^T)^T = Wk Wq^T, hi
__device__ __nv_bfloat16 g_Mtl[(size_t)Hd * Hd];    // lo
__device__ __nv_bfloat16 g_Wvth[(size_t)Hd * Hd];   // Wv^T hi
__device__ __nv_bfloat16 g_Wvtl[(size_t)Hd * Hd];   // Wv^T lo
__device__ float g_vk[Hd];                          // Wk @ bq
__device__ float g_u[(size_t)RTOT * Hd];            // z @ M  (fp32)
__device__ __nv_bfloat16 g_yh[(size_t)Bsz * Hd];    // y hi
__device__ __nv_bfloat16 g_yl[(size_t)Bsz * Hd];    // y lo

// ============================================================
// helpers
// ============================================================
__device__ __forceinline__ uint32_t smem_u32(const void* p) {
    uint32_t a;
    asm("{ .reg .u64 t; cvta.to.shared.u64 t, %1; cvt.u32.u64 %0, t; }" : "=r"(a) : "l"(p));
    return a;
}
__device__ __forceinline__ void cp16(uint32_t dst, const void* src) {
    asm volatile("cp.async.cg.shared.global [%0], [%1], 16;" :: "r"(dst), "l"(src));
}
__device__ __forceinline__ void cp_commit() { asm volatile("cp.async.commit_group;" ::: "memory"); }
template <int N>
__device__ __forceinline__ void cp_wait() { asm volatile("cp.async.wait_group %0;" :: "n"(N) : "memory"); }
__device__ __forceinline__ void mma16816(float (&d)[4], const uint32_t (&a)[4],
                                         uint32_t b0, uint32_t b1) {
    asm volatile(
        "mma.sync.aligned.m16n8k16.row.col.f32.bf16.bf16.f32 "
        "{%0,%1,%2,%3}, {%4,%5,%6,%7}, {%8,%9}, {%0,%1,%2,%3};"
        : "+f"(d[0]), "+f"(d[1]), "+f"(d[2]), "+f"(d[3])
        : "r"(a[0]), "r"(a[1]), "r"(a[2]), "r"(a[3]), "r"(b0), "r"(b1));
}
__device__ __forceinline__ const float* fsel(const float* f1, const float* f2,
                                             const float* f3, const float* f4, int t) {
    return t == 0 ? f1 : t == 1 ? f2 : t == 2 ? f3 : f4;
}
__device__ __forceinline__ void split_bf16(float v, __nv_bfloat16& h, __nv_bfloat16& l) {
    h = __float2bfloat16(v);
    l = __float2bfloat16(v - __bfloat162float(h));
}

// ============================================================
// prep_z: f1..f4 -> g_zh/g_zl, row r = b*4+t
// ============================================================
__global__ __launch_bounds__(256) void prep_z_kernel(const float* __restrict__ f1,
                                                     const float* __restrict__ f2,
                                                     const float* __restrict__ f3,
                                                     const float* __restrict__ f4) {
    size_t gid = (size_t)blockIdx.x * 256 + threadIdx.x;   // over RTOT * (Hd/4)
    int r = (int)(gid >> 8);
    int jj = (int)(gid & 255);
    const float* src = fsel(f1, f2, f3, f4, r & 3) + (size_t)(r >> 2) * Hd;
    float4 v = ((const float4*)src)[jj];
    __nv_bfloat16 hx, lx, hy, ly, hz, lz, hw, lw;
    split_bf16(v.x, hx, lx); split_bf16(v.y, hy, ly);
    split_bf16(v.z, hz, lz); split_bf16(v.w, hw, lw);
    __nv_bfloat162* dh = (__nv_bfloat162*)(g_zh + (size_t)r * Hd + jj * 4);
    __nv_bfloat162* dl = (__nv_bfloat162*)(g_zl + (size_t)r * Hd + jj * 4);
    dh[0] = __halves2bfloat162(hx, hy); dh[1] = __halves2bfloat162(hz, hw);
    dl[0] = __halves2bfloat162(lx, ly); dl[1] = __halves2bfloat162(lz, lw);
}

// ============================================================
// Mt = Wk @ Wq^T -> bf16 hi/lo (SIMT fp32 GEMM, small: 1024^3)
// ============================================================
#define BM 128
#define BN 128
#define BK 8
#define TM 8
#define TN 8
__global__ __launch_bounds__(256) void mt_gemm_kernel(const float* __restrict__ Wk,
                                                      const float* __restrict__ Wq) {
    __shared__ float As[BK][BM];
    __shared__ float Bs[BK][BN];
    const int tid = threadIdx.x;
    const int brow = blockIdx.y * BM;
    const int bcol = blockIdx.x * BN;
    const int lrow = tid >> 1, lcol = (tid & 1) * 4;
    const float* aptr = Wk + (size_t)(brow + lrow) * Hd + lcol;
    const float* bptr = Wq + (size_t)(bcol + lrow) * Hd + lcol;
    const int trow = (tid >> 4) * TM, tcol = (tid & 15) * TN;
    float acc[TM][TN] = {};
    for (int k0 = 0; k0 < Hd; k0 += BK) {
        float4 av = *(const float4*)(aptr + k0);
        As[lcol + 0][lrow] = av.x; As[lcol + 1][lrow] = av.y;
        As[lcol + 2][lrow] = av.z; As[lcol + 3][lrow] = av.w;
        float4 bv4 = *(const float4*)(bptr + k0);
        Bs[lcol + 0][lrow] = bv4.x; Bs[lcol + 1][lrow] = bv4.y;
        Bs[lcol + 2][lrow] = bv4.z; Bs[lcol + 3][lrow] = bv4.w;
        __syncthreads();
#pragma unroll
        for (int kk = 0; kk < BK; kk++) {
            float a[TM], b[TN];
            *(float4*)&a[0] = *(const float4*)&As[kk][trow];
            *(float4*)&a[4] = *(const float4*)&As[kk][trow + 4];
            *(float4*)&b[0] = *(const float4*)&Bs[kk][tcol];
            *(float4*)&b[4] = *(const float4*)&Bs[kk][tcol + 4];
#pragma unroll
            for (int i = 0; i < TM; i++)
#pragma unroll
                for (int j = 0; j < TN; j++) acc[i][j] += a[i] * b[j];
        }
        __syncthreads();
    }
#pragma unroll
    for (int i = 0; i < TM; i++) {
        size_t off = (size_t)(brow + trow + i) * Hd + bcol + tcol;
#pragma unroll
        for (int j = 0; j < TN; j += 2) {
            __nv_bfloat16 h0, l0, h1, l1;
            split_bf16(acc[i][j], h0, l0);
            split_bf16(acc[i][j + 1], h1, l1);
            *(__nv_bfloat162*)(g_Mth + off + j) = __halves2bfloat162(h0, h1);
            *(__nv_bfloat162*)(g_Mtl + off + j) = __halves2bfloat162(l0, l1);
        }
    }
}

// ============================================================
// Wvt[n][k] = Wv[k][n] -> bf16 hi/lo
// ============================================================
__global__ __launch_bounds__(256) void wvt_kernel(const float* __restrict__ Wv) {
    __shared__ float tile[32][33];
    const int tx = threadIdx.x & 31, ty8 = threadIdx.x >> 5;  // 32x8
    const int n0 = blockIdx.x * 32, k0 = blockIdx.y * 32;
#pragma unroll
    for (int r = 0; r < 4; r++) {
        int ky = ty8 + r * 8;
        tile[ky][tx] = Wv[(size_t)(k0 + ky) * Hd + n0 + tx];
    }
    __syncthreads();
#pragma unroll
    for (int r = 0; r < 4; r++) {
        int ny = ty8 + r * 8;
        float v = tile[tx][ny];
        __nv_bfloat16 h, l;
        split_bf16(v, h, l);
        g_Wvth[(size_t)(n0 + ny) * Hd + k0 + tx] = h;
        g_Wvtl[(size_t)(n0 + ny) * Hd + k0 + tx] = l;
    }
}

// ============================================================
// vk = Wk @ bq
// ============================================================
__global__ __launch_bounds__(256) void vk_kernel(const float* __restrict__ Wk,
                                                 const float* __restrict__ bq) {
    int warp = threadIdx.x >> 5, lane = threadIdx.x & 31;
    int row = blockIdx.x * 8 + warp;
    float s = 0.f;
    for (int m = lane; m < Hd; m += 32) s += Wk[(size_t)row * Hd + m] * bq[m];
#pragma unroll
    for (int off = 16; off; off >>= 1) s += __shfl_xor_sync(0xffffffffu, s, off);
    if (lane == 0) g_vk[row] = s;
}

// ============================================================
// HMMA bf16x3 GEMM body (pointers bound IN DEVICE CODE).
//   C[rows,1024] = A@B^T (+ biasScale*bias)
//   CTA tile 128x128 (max reuse), Kc=16, 8 warps (2m x 4n), warp tile 64x32.
//   Double-buffered 48KB SMEM; loader is cp.async (no prefetch registers)
//   so ptxas fits 128 regs -> 2 CTAs/SM via __launch_bounds__(256,2).
//   LDS.32 fragment loads (R9-proven), pass-major MMA order.
// ============================================================
#define HK 16
#define HLD 24                       // row stride bf16 (48B): conflict-free frags
#define SM_BUF (128 * HLD * 2)       // 6144 B per buffer
#define SM_STG (4 * SM_BUF)          // 24576 B per stage
template <bool BIAS>
__device__ __forceinline__ void hmma_gemm_body(
    const __nv_bfloat16* __restrict__ Ah, const __nv_bfloat16* __restrict__ Al,
    const __nv_bfloat16* __restrict__ Bh, const __nv_bfloat16* __restrict__ Bl,
    float* __restrict__ C, const float* __restrict__ bias, float biasScale) {
    __shared__ __nv_bfloat16 sm[2][4][128][HLD];   // [stage][buf][row][col] 48KB

    const int tid = threadIdx.x;
    const int wid = tid >> 5, lane = tid & 31;
    const int warp_m = wid & 1, warp_n = wid >> 1;  // 2m x 4n, warp tile 64x32
    const int g = lane >> 2, tg = lane & 3;
    const int row0 = blockIdx.y * 128, n0 = blockIdx.x * 128;
    const uint32_t sbase = smem_u32(sm);

    const __nv_bfloat16* ptr[4] = {Ah + (size_t)row0 * Hd, Al + (size_t)row0 * Hd,
                                   Bh + (size_t)n0 * Hd,  Bl + (size_t)n0 * Hd};

    // cp.async loader: per stage 4 bufs x 128 rows x 2 granules(16B); 4/thread
    const int lrow = tid >> 1, lq = tid & 1;
    const size_t goff = (size_t)lrow * Hd + lq * 8;
    const uint32_t soff = (uint32_t)(lrow * (HLD * 2) + lq * 16);

    auto cp_chunk = [&](int c, int s) {
        const size_t o = goff + (size_t)c * HK;
        const uint32_t d = sbase + s * SM_STG + soff;
#pragma unroll
        for (int b = 0; b < 4; b++) cp16(d + b * SM_BUF, ptr[b] + o);
    };

    const int arow = warp_m * 64 + g;
    const int brow = warp_n * 32 + g;
    const int kc = 2 * tg;
    float acc[4][4][4] = {};   // [mf][nf][reg]

    cp_chunk(0, 0);
    cp_commit();

    for (int c = 0; c < Hd / HK; c++) {
        const int s = c & 1;
        cp_wait<0>();                 // chunk c resident
        __syncthreads();              // visible to all; all warps done with s (WAR)
        if (c < Hd / HK - 1) { cp_chunk(c + 1, s ^ 1); cp_commit(); }

        uint32_t ah[4][4], al[4][4], bh[4][2], bl[4][2];
#pragma unroll
        for (int mf = 0; mf < 4; mf++) {
            const int r = arow + mf * 16;
            ah[mf][0] = *(const uint32_t*)&sm[s][0][r][kc];
            ah[mf][1] = *(const uint32_t*)&sm[s][0][r + 8][kc];
            ah[mf][2] = *(const uint32_t*)&sm[s][0][r][kc + 8];
            ah[mf][3] = *(const uint32_t*)&sm[s][0][r + 8][kc + 8];
            al[mf][0] = *(const uint32_t*)&sm[s][1][r][kc];
            al[mf][1] = *(const uint32_t*)&sm[s][1][r + 8][kc];
            al[mf][2] = *(const uint32_t*)&sm[s][1][r][kc + 8];
            al[mf][3] = *(const uint32_t*)&sm[s][1][r + 8][kc + 8];
        }
#pragma unroll
        for (int nf = 0; nf < 4; nf++) {
            const int r = brow + nf * 8;
            bh[nf][0] = *(const uint32_t*)&sm[s][2][r][kc];
            bh[nf][1] = *(const uint32_t*)&sm[s][2][r][kc + 8];
            bl[nf][0] = *(const uint32_t*)&sm[s][3][r][kc];
            bl[nf][1] = *(const uint32_t*)&sm[s][3][r][kc + 8];
        }
        // pass-major: consecutive MMAs hit different accumulators
#pragma unroll
        for (int mf = 0; mf < 4; mf++)
#pragma unroll
            for (int nf = 0; nf < 4; nf++)
                mma16816(acc[mf][nf], ah[mf], bh[nf][0], bh[nf][1]);
#pragma unroll
        for (int mf = 0; mf < 4; mf++)
#pragma unroll
            for (int nf = 0; nf < 4; nf++)
                mma16816(acc[mf][nf], al[mf], bh[nf][0], bh[nf][1]);
#pragma unroll
        for (int mf = 0; mf < 4; mf++)
#pragma unroll
            for (int nf = 0; nf < 4; nf++)
                mma16816(acc[mf][nf], ah[mf], bl[nf][0], bl[nf][1]);

        __syncthreads();              // all warps done reading s before overwrite
    }

    // epilogue (R9-proven): c0,c1 = row g cols 2tg..; c2,c3 = row g+8
#pragma unroll
    for (int mf = 0; mf < 4; mf++) {
        const int rg = row0 + warp_m * 64 + mf * 16 + g;
#pragma unroll
        for (int nf = 0; nf < 4; nf++) {
            const int cg = n0 + warp_n * 32 + nf * 8 + tg * 2;
            float2 v0 = make_float2(acc[mf][nf][0], acc[mf][nf][1]);
            float2 v1 = make_float2(acc[mf][nf][2], acc[mf][nf][3]);
            if (BIAS) {
                float b0v = biasScale * bias[cg], b1v = biasScale * bias[cg + 1];
                v0.x += b0v; v0.y += b1v; v1.x += b0v; v1.y += b1v;
            }
            *(float2*)(C + (size_t)rg * Hd + cg) = v0;
            *(float2*)(C + (size_t)(rg + 8) * Hd + cg) = v1;
        }
    }
}

// u = z @ M : all operands are __device__ globals, bound in device code
__global__ __launch_bounds__(256, 2) void u_hmma_kernel() {
    hmma_gemm_body<false>(g_zh, g_zl, g_Mth, g_Mtl, g_u, nullptr, 0.f);
}
// x = y @ Wv^T + 4*bv : globals bound in device code; bv/xout are harness ptrs
__global__ __launch_bounds__(256, 2) void x_hmma_kernel(const float* __restrict__ bv,
                                                        float* __restrict__ xout) {
    hmma_gemm_body<true>(g_yh, g_yl, g_Wvth, g_Wvtl, xout, bv, 4.f);
}

// ============================================================
// per-batch attention, register-resident (R12-proven):
// thread owns 8 contiguous j; logits via u,z; softmax; y bf16 split
// ============================================================
__global__ __launch_bounds__(128) void attn_kernel(const float* __restrict__ f1,
                                                   const float* __restrict__ f2,
                                                   const float* __restrict__ f3,
                                                   const float* __restrict__ f4) {
    const int b = blockIdx.x, tid = threadIdx.x;
    const int jb = tid * 8;

    float z[4][8], u[4][8];
#pragma unroll
    for (int t = 0; t < 4; t++) {
        const float4* zp = (const float4*)(fsel(f1, f2, f3, f4, t) + (size_t)b * Hd + jb);
        const float4* up = (const float4*)(g_u + ((size_t)b * 4 + t) * Hd + jb);
        *(float4*)&z[t][0] = zp[0]; *(float4*)&z[t][4] = zp[1];
        *(float4*)&u[t][0] = up[0]; *(float4*)&u[t][4] = up[1];
    }
    float vk8[8];
    *(float4*)&vk8[0] = *(const float4*)(g_vk + jb);
    *(float4*)&vk8[4] = *(const float4*)(g_vk + jb + 4);

    float aG[16] = {}, aC[4] = {};
#pragma unroll
    for (int j = 0; j < 8; j++) {
#pragma unroll
        for (int t = 0; t < 4; t++)
#pragma unroll
            for (int s = 0; s < 4; s++) aG[t * 4 + s] += u[t][j] * z[s][j];
#pragma unroll
        for (int s = 0; s < 4; s++) aC[s] += z[s][j] * vk8[j];
    }
#pragma unroll
    for (int a = 0; a < 16; a++)
#pragma unroll
        for (int off = 16; off; off >>= 1) aG[a] += __shfl_xor_sync(0xffffffffu, aG[a], off);
#pragma unroll
    for (int a = 0; a < 4; a++)
#pragma unroll
        for (int off = 16; off; off >>= 1) aC[a] += __shfl_xor_sync(0xffffffffu, aC[a], off);

    __shared__ float rbuf[4][20];
    __shared__ float sw[4];
    const int warp = tid >> 5, lane = tid & 31;
    if (lane == 0) {
#pragma unroll
        for (int a = 0; a < 16; a++) rbuf[warp][a] = aG[a];
#pragma unroll
        for (int a = 0; a < 4; a++) rbuf[warp][16 + a] = aC[a];
    }
    __syncthreads();
    if (tid == 0) {
        float L[20];
#pragma unroll
        for (int a = 0; a < 20; a++) L[a] = rbuf[0][a] + rbuf[1][a] + rbuf[2][a] + rbuf[3][a];
        float w[4] = {0.f, 0.f, 0.f, 0.f};
#pragma unroll
        for (int t = 0; t < 4; t++) {
            float l0 = L[t * 4 + 0] + L[16];
            float l1 = L[t * 4 + 1] + L[17];
            float l2 = L[t * 4 + 2] + L[18];
            float l3 = L[t * 4 + 3] + L[19];
            float m = fmaxf(fmaxf(l0, l1), fmaxf(l2, l3));
            float e0 = expf(l0 - m), e1 = expf(l1 - m), e2 = expf(l2 - m), e3 = expf(l3 - m);
            float inv = 1.f / (e0 + e1 + e2 + e3);
            w[0] += e0 * inv; w[1] += e1 * inv; w[2] += e2 * inv; w[3] += e3 * inv;
        }
        sw[0] = w[0]; sw[1] = w[1]; sw[2] = w[2]; sw[3] = w[3];
    }
    __syncthreads();
    const float w0 = sw[0], w1 = sw[1], w2 = sw[2], w3 = sw[3];

    __nv_bfloat162 oh[4], ol[4];
#pragma unroll
    for (int jj = 0; jj < 4; jj++) {
        float o0 = w0 * z[0][jj * 2]     + w1 * z[1][jj * 2]     + w2 * z[2][jj * 2]     + w3 * z[3][jj * 2];
        float o1 = w0 * z[0][jj * 2 + 1] + w1 * z[1][jj * 2 + 1] + w2 * z[2][jj * 2 + 1] + w3 * z[3][jj * 2 + 1];
        __nv_bfloat16 h0, l0, h1, l1;
        split_bf16(o0, h0, l0); split_bf16(o1, h1, l1);
        oh[jj] = __halves2bfloat162(h0, h1);
        ol[jj] = __halves2bfloat162(l0, l1);
    }
    *(uint2*)(g_yh + (size_t)b * Hd + jb)     = *(uint2*)&oh[0];
    *(uint2*)(g_yh + (size_t)b * Hd + jb + 4) = *(uint2*)&oh[2];
    *(uint2*)(g_yl + (size_t)b * Hd + jb)     = *(uint2*)&ol[0];
    *(uint2*)(g_yl + (size_t)b * Hd + jb + 4) = *(uint2*)&ol[2];
}

// ============================================================
// out = softmax(x @ Wfc + bfc)
// ============================================================
__global__ __launch_bounds__(128) void fc_kernel(const float* __restrict__ x,
                                                 const float* __restrict__ Wfc,
                                                 const float* __restrict__ bfc,
                                                 float* __restrict__ oout) {
    __shared__ float sxT[Hd][8];
    const int tid = threadIdx.x;
    const int row0 = blockIdx.x * 8;
    for (int idx = tid; idx < 8 * Hd; idx += 128) {
        int r = idx >> 10;
        int k = idx & (Hd - 1);
        sxT[k][r] = x[(size_t)(row0 + r) * Hd + k];
    }
    __syncthreads();
    float acc[8] = {};
#pragma unroll 4
    for (int k = 0; k < Hd; k++) {
        float wv = Wfc[(size_t)k * ODIM + tid];
        float4 lo = *(const float4*)&sxT[k][0];
        float4 hi = *(const float4*)&sxT[k][4];
        acc[0] += lo.x * wv; acc[1] += lo.y * wv; acc[2] += lo.z * wv; acc[3] += lo.w * wv;
        acc[4] += hi.x * wv; acc[5] += hi.y * wv; acc[6] += hi.z * wv; acc[7] += hi.w * wv;
    }
    const float bb = bfc[tid];
#pragma unroll
    for (int r = 0; r < 8; r++) acc[r] += bb;

    __shared__ float slog[8][128];
#pragma unroll
    for (int r = 0; r < 8; r++) slog[r][tid] = acc[r];
    __syncthreads();
    __shared__ float smax[8], sinv[8];
    const int warp = tid >> 5, lane = tid & 31;
#pragma unroll
    for (int rr = 0; rr < 2; rr++) {
        int r = warp * 2 + rr;
        float v0 = slog[r][lane], v1 = slog[r][lane + 32];
        float v2 = slog[r][lane + 64], v3 = slog[r][lane + 96];
        float m = fmaxf(fmaxf(v0, v1), fmaxf(v2, v3));
#pragma unroll
        for (int off = 16; off; off >>= 1) m = fmaxf(m, __shfl_xor_sync(0xffffffffu, m, off));
        float s = expf(v0 - m) + expf(v1 - m) + expf(v2 - m) + expf(v3 - m);
#pragma unroll
        for (int off = 16; off; off >>= 1) s += __shfl_xor_sync(0xffffffffu, s, off);
        if (lane == 0) { smax[r] = m; sinv[r] = 1.f / s; }
    }
    __syncthreads();
#pragma unroll
    for (int r = 0; r < 8; r++)
        oout[(size_t)(row0 + r) * ODIM + tid] = expf(acc[r] - smax[r]) * sinv[r];
}

// ============================================================
extern "C" void kernel_launch(void* const* d_in, const int* in_sizes, int n_in,
                              void* d_out, int out_size) {
    (void)in_sizes; (void)n_in; (void)out_size;
    const float* f1  = (const float*)d_in[0];
    const float* f2  = (const float*)d_in[1];
    const float* f3  = (const float*)d_in[2];
    const float* f4  = (const float*)d_in[3];
    const float* Wq  = (const float*)d_in[4];
    const float* bq  = (const float*)d_in[5];
    const float* Wk  = (const float*)d_in[6];
    // d_in[7] = bk: cancels inside softmax — unused
    const float* Wv  = (const float*)d_in[8];
    const float* bv  = (const float*)d_in[9];
    const float* Wfc = (const float*)d_in[10];
    const float* bfc = (const float*)d_in[11];

    float* xout = (float*)d_out;                 // [B, H]
    float* oout = xout + (size_t)Bsz * Hd;       // [B, OUT]

    // bf16 split conversions + small precomputes
    prep_z_kernel<<<(RTOT * (Hd / 4)) / 256, 256>>>(f1, f2, f3, f4);
    mt_gemm_kernel<<<dim3(Hd / BN, Hd / BM), 256>>>(Wk, Wq);
    wvt_kernel<<<dim3(Hd / 32, Hd / 32), 256>>>(Wv);

    // u = z @ M  (HMMA bf16x3, 128x128, cp.async, 2 CTAs/SM) — 4th launch for ncu
    u_hmma_kernel<<<dim3(Hd / 128, RTOT / 128), 256>>>();

    // vk needed only by attn
    vk_kernel<<<Hd / 8, 256>>>(Wk, bq);

    // attention reduce -> y (bf16 split, register-resident)
    attn_kernel<<<Bsz, 128>>>(f1, f2, f3, f4);

    // x = y @ Wv + 4*bv  (HMMA bf16x3)
    x_hmma_kernel<<<dim3(Hd / 128, Bsz / 128), 256>>>(bv, xout);

    // out = softmax(x @ Wfc + bfc)
    fc_kernel<<<Bsz / 8, 128>>>(xout, Wfc, bfc, oout);
}

// round 17
// speedup vs baseline: 1.6395x; 1.0278x over previous
#include <cuda_runtime.h>
#include <cuda_bf16.h>
#include <cstdint>

#define Bsz 16384
#define Hd  1024
#define ODIM 128
#define RTOT (Bsz * 4)

// ---- scratch (static __device__ — no allocations allowed) ----
__device__ __nv_bfloat16 g_zh[(size_t)RTOT * Hd];   // z hi
__device__ __nv_bfloat16 g_zl[(size_t)RTOT * Hd];   // z lo
__device__ __nv_bfloat16 g_Mth[(size_t)Hd * Hd];    // (WqWk^T)^T = Wk Wq^T, hi
__device__ __nv_bfloat16 g_Mtl[(size_t)Hd * Hd];    // lo
__device__ __nv_bfloat16 g_Wvth[(size_t)Hd * Hd];   // Wv^T hi
__device__ __nv_bfloat16 g_Wvtl[(size_t)Hd * Hd];   // Wv^T lo
__device__ float g_vk[Hd];                          // Wk @ bq
__device__ float g_u[(size_t)RTOT * Hd];            // z @ M  (fp32)
__device__ __nv_bfloat16 g_yh[(size_t)Bsz * Hd];    // y hi
__device__ __nv_bfloat16 g_yl[(size_t)Bsz * Hd];    // y lo

// ============================================================
// helpers
// ============================================================
__device__ __forceinline__ uint32_t smem_u32(const void* p) {
    uint32_t a;
    asm("{ .reg .u64 t; cvta.to.shared.u64 t, %1; cvt.u32.u64 %0, t; }" : "=r"(a) : "l"(p));
    return a;
}
__device__ __forceinline__ void cp16(uint32_t dst, const void* src) {
    asm volatile("cp.async.cg.shared.global [%0], [%1], 16;" :: "r"(dst), "l"(src));
}
__device__ __forceinline__ void cp_commit() { asm volatile("cp.async.commit_group;" ::: "memory"); }
template <int N>
__device__ __forceinline__ void cp_wait() { asm volatile("cp.async.wait_group %0;" :: "n"(N) : "memory"); }
__device__ __forceinline__ void mma16816(float (&d)[4], const uint32_t (&a)[4],
                                         uint32_t b0, uint32_t b1) {
    asm volatile(
        "mma.sync.aligned.m16n8k16.row.col.f32.bf16.bf16.f32 "
        "{%0,%1,%2,%3}, {%4,%5,%6,%7}, {%8,%9}, {%0,%1,%2,%3};"
        : "+f"(d[0]), "+f"(d[1]), "+f"(d[2]), "+f"(d[3])
        : "r"(a[0]), "r"(a[1]), "r"(a[2]), "r"(a[3]), "r"(b0), "r"(b1));
}
__device__ __forceinline__ const float* fsel(const float* f1, const float* f2,
                                             const float* f3, const float* f4, int t) {
    return t == 0 ? f1 : t == 1 ? f2 : t == 2 ? f3 : f4;
}
__device__ __forceinline__ void split_bf16(float v, __nv_bfloat16& h, __nv_bfloat16& l) {
    h = __float2bfloat16(v);
    l = __float2bfloat16(v - __bfloat162float(h));
}

// ============================================================
// prep_z: f1..f4 -> g_zh/g_zl, row r = b*4+t
// ============================================================
__global__ __launch_bounds__(256) void prep_z_kernel(const float* __restrict__ f1,
                                                     const float* __restrict__ f2,
                                                     const float* __restrict__ f3,
                                                     const float* __restrict__ f4) {
    size_t gid = (size_t)blockIdx.x * 256 + threadIdx.x;   // over RTOT * (Hd/4)
    int r = (int)(gid >> 8);
    int jj = (int)(gid & 255);
    const float* src = fsel(f1, f2, f3, f4, r & 3) + (size_t)(r >> 2) * Hd;
    float4 v = ((const float4*)src)[jj];
    __nv_bfloat16 hx, lx, hy, ly, hz, lz, hw, lw;
    split_bf16(v.x, hx, lx); split_bf16(v.y, hy, ly);
    split_bf16(v.z, hz, lz); split_bf16(v.w, hw, lw);
    __nv_bfloat162* dh = (__nv_bfloat162*)(g_zh + (size_t)r * Hd + jj * 4);
    __nv_bfloat162* dl = (__nv_bfloat162*)(g_zl + (size_t)r * Hd + jj * 4);
    dh[0] = __halves2bfloat162(hx, hy); dh[1] = __halves2bfloat162(hz, hw);
    dl[0] = __halves2bfloat162(lx, ly); dl[1] = __halves2bfloat162(lz, lw);
}

// ============================================================
// Mt = Wk @ Wq^T -> bf16 hi/lo (SIMT fp32 GEMM, small: 1024^3)
// ============================================================
#define BM 128
#define BN 128
#define BK 8
#define TM 8
#define TN 8
__global__ __launch_bounds__(256) void mt_gemm_kernel(const float* __restrict__ Wk,
                                                      const float* __restrict__ Wq) {
    __shared__ float As[BK][BM];
    __shared__ float Bs[BK][BN];
    const int tid = threadIdx.x;
    const int brow = blockIdx.y * BM;
    const int bcol = blockIdx.x * BN;
    const int lrow = tid >> 1, lcol = (tid & 1) * 4;
    const float* aptr = Wk + (size_t)(brow + lrow) * Hd + lcol;
    const float* bptr = Wq + (size_t)(bcol + lrow) * Hd + lcol;
    const int trow = (tid >> 4) * TM, tcol = (tid & 15) * TN;
    float acc[TM][TN] = {};
    for (int k0 = 0; k0 < Hd; k0 += BK) {
        float4 av = *(const float4*)(aptr + k0);
        As[lcol + 0][lrow] = av.x; As[lcol + 1][lrow] = av.y;
        As[lcol + 2][lrow] = av.z; As[lcol + 3][lrow] = av.w;
        float4 bv4 = *(const float4*)(bptr + k0);
        Bs[lcol + 0][lrow] = bv4.x; Bs[lcol + 1][lrow] = bv4.y;
        Bs[lcol + 2][lrow] = bv4.z; Bs[lcol + 3][lrow] = bv4.w;
        __syncthreads();
#pragma unroll
        for (int kk = 0; kk < BK; kk++) {
            float a[TM], b[TN];
            *(float4*)&a[0] = *(const float4*)&As[kk][trow];
            *(float4*)&a[4] = *(const float4*)&As[kk][trow + 4];
            *(float4*)&b[0] = *(const float4*)&Bs[kk][tcol];
            *(float4*)&b[4] = *(const float4*)&Bs[kk][tcol + 4];
#pragma unroll
            for (int i = 0; i < TM; i++)
#pragma unroll
                for (int j = 0; j < TN; j++) acc[i][j] += a[i] * b[j];
        }
        __syncthreads();
    }
#pragma unroll
    for (int i = 0; i < TM; i++) {
        size_t off = (size_t)(brow + trow + i) * Hd + bcol + tcol;
#pragma unroll
        for (int j = 0; j < TN; j += 2) {
            __nv_bfloat16 h0, l0, h1, l1;
            split_bf16(acc[i][j], h0, l0);
            split_bf16(acc[i][j + 1], h1, l1);
            *(__nv_bfloat162*)(g_Mth + off + j) = __halves2bfloat162(h0, h1);
            *(__nv_bfloat162*)(g_Mtl + off + j) = __halves2bfloat162(l0, l1);
        }
    }
}

// ============================================================
// Wvt[n][k] = Wv[k][n] -> bf16 hi/lo
// ============================================================
__global__ __launch_bounds__(256) void wvt_kernel(const float* __restrict__ Wv) {
    __shared__ float tile[32][33];
    const int tx = threadIdx.x & 31, ty8 = threadIdx.x >> 5;  // 32x8
    const int n0 = blockIdx.x * 32, k0 = blockIdx.y * 32;
#pragma unroll
    for (int r = 0; r < 4; r++) {
        int ky = ty8 + r * 8;
        tile[ky][tx] = Wv[(size_t)(k0 + ky) * Hd + n0 + tx];
    }
    __syncthreads();
#pragma unroll
    for (int r = 0; r < 4; r++) {
        int ny = ty8 + r * 8;
        float v = tile[tx][ny];
        __nv_bfloat16 h, l;
        split_bf16(v, h, l);
        g_Wvth[(size_t)(n0 + ny) * Hd + k0 + tx] = h;
        g_Wvtl[(size_t)(n0 + ny) * Hd + k0 + tx] = l;
    }
}

// ============================================================
// vk = Wk @ bq
// ============================================================
__global__ __launch_bounds__(256) void vk_kernel(const float* __restrict__ Wk,
                                                 const float* __restrict__ bq) {
    int warp = threadIdx.x >> 5, lane = threadIdx.x & 31;
    int row = blockIdx.x * 8 + warp;
    float s = 0.f;
    for (int m = lane; m < Hd; m += 32) s += Wk[(size_t)row * Hd + m] * bq[m];
#pragma unroll
    for (int off = 16; off; off >>= 1) s += __shfl_xor_sync(0xffffffffu, s, off);
    if (lane == 0) g_vk[row] = s;
}

// ============================================================
// HMMA bf16x3 GEMM — Kc=32 dynamic-SMEM variant (80KB, 2 stages):
//   CTA 128x128, 8 warps (2m x 4n), warp 64x32, cp.async loader,
//   one __syncthreads per chunk (32 chunks), pass-major MMA.
//   HLD2=40 (80B rows): banks (20g+tg)%32 all distinct -> conflict-free.
// ============================================================
#define HK2 32
#define HLD2 40
#define SMB2 (128 * HLD2 * 2)   // 10240 B per buffer
#define SMS2 (4 * SMB2)         // 40960 B per stage
#define SMEM_DYN (2 * SMS2)     // 81920 B

template <bool BIAS>
__device__ __forceinline__ void hmma_gemm_body_dyn(
    const __nv_bfloat16* __restrict__ Ah, const __nv_bfloat16* __restrict__ Al,
    const __nv_bfloat16* __restrict__ Bh, const __nv_bfloat16* __restrict__ Bl,
    float* __restrict__ C, const float* __restrict__ bias, float biasScale) {
    extern __shared__ __nv_bfloat16 dsm[];   // [2][4][128][HLD2]
    const uint32_t sbase = smem_u32(dsm);

    const int tid = threadIdx.x;
    const int wid = tid >> 5, lane = tid & 31;
    const int warp_m = wid & 1, warp_n = wid >> 1;  // 2m x 4n, warp tile 64x32
    const int g = lane >> 2, tg = lane & 3;
    const int row0 = blockIdx.y * 128, n0 = blockIdx.x * 128;

    const __nv_bfloat16* ptr[4] = {Ah + (size_t)row0 * Hd, Al + (size_t)row0 * Hd,
                                   Bh + (size_t)n0 * Hd,  Bl + (size_t)n0 * Hd};

    // loader: per stage 4 bufs x 128 rows x 4 granules(16B) = 2048; 8/thread.
    // thread covers 2 granule-slots in each of 4 bufs: idx = tid*2, tid*2+1
    const int i0 = tid * 2;
    const int lrow = i0 >> 2, lq0 = i0 & 3;          // lq1 = lq0+1 (tid*2 even)
    const size_t goff = (size_t)lrow * Hd + lq0 * 8;
    const uint32_t soff = (uint32_t)(lrow * (HLD2 * 2) + lq0 * 16);

    auto cp_chunk = [&](int c, int s) {
        const size_t o = goff + (size_t)c * HK2;
        const uint32_t d = sbase + s * SMS2 + soff;
#pragma unroll
        for (int b = 0; b < 4; b++) {
            cp16(d + b * SMB2, ptr[b] + o);
            cp16(d + b * SMB2 + 16, ptr[b] + o + 8);
        }
    };

    // fragment LDS element offsets within a stage
    const int arow = warp_m * 64 + g;
    const int brow = warp_n * 32 + g;
    float acc[4][4][4] = {};   // [mf][nf][reg]

    cp_chunk(0, 0);
    cp_commit();

    for (int c = 0; c < Hd / HK2; c++) {
        const int s = c & 1;
        cp_wait<0>();
        __syncthreads();              // chunk c visible; all warps past reads of s^1
        if (c < Hd / HK2 - 1) { cp_chunk(c + 1, s ^ 1); cp_commit(); }

        const __nv_bfloat16* st = dsm + (size_t)s * (SMS2 / 2);  // element offset
#pragma unroll
        for (int ks = 0; ks < 2; ks++) {
            const int kc = ks * 16 + 2 * tg;
            uint32_t ah[4][4], al[4][4], bh[4][2], bl[4][2];
#pragma unroll
            for (int mf = 0; mf < 4; mf++) {
                const int r = arow + mf * 16;
                const __nv_bfloat16* ph = st + 0 * (SMB2 / 2) + (size_t)r * HLD2 + kc;
                const __nv_bfloat16* pl = st + 1 * (SMB2 / 2) + (size_t)r * HLD2 + kc;
                ah[mf][0] = *(const uint32_t*)(ph);
                ah[mf][1] = *(const uint32_t*)(ph + 8 * HLD2);
                ah[mf][2] = *(const uint32_t*)(ph + 8);
                ah[mf][3] = *(const uint32_t*)(ph + 8 * HLD2 + 8);
                al[mf][0] = *(const uint32_t*)(pl);
                al[mf][1] = *(const uint32_t*)(pl + 8 * HLD2);
                al[mf][2] = *(const uint32_t*)(pl + 8);
                al[mf][3] = *(const uint32_t*)(pl + 8 * HLD2 + 8);
            }
#pragma unroll
            for (int nf = 0; nf < 4; nf++) {
                const int r = brow + nf * 8;
                const __nv_bfloat16* ph = st + 2 * (SMB2 / 2) + (size_t)r * HLD2 + kc;
                const __nv_bfloat16* pl = st + 3 * (SMB2 / 2) + (size_t)r * HLD2 + kc;
                bh[nf][0] = *(const uint32_t*)(ph);
                bh[nf][1] = *(const uint32_t*)(ph + 8);
                bl[nf][0] = *(const uint32_t*)(pl);
                bl[nf][1] = *(const uint32_t*)(pl + 8);
            }
            // pass-major
#pragma unroll
            for (int mf = 0; mf < 4; mf++)
#pragma unroll
                for (int nf = 0; nf < 4; nf++)
                    mma16816(acc[mf][nf], ah[mf], bh[nf][0], bh[nf][1]);
#pragma unroll
            for (int mf = 0; mf < 4; mf++)
#pragma unroll
                for (int nf = 0; nf < 4; nf++)
                    mma16816(acc[mf][nf], al[mf], bh[nf][0], bh[nf][1]);
#pragma unroll
            for (int mf = 0; mf < 4; mf++)
#pragma unroll
                for (int nf = 0; nf < 4; nf++)
                    mma16816(acc[mf][nf], ah[mf], bl[nf][0], bl[nf][1]);
        }
    }

    // epilogue (R9-proven)
#pragma unroll
    for (int mf = 0; mf < 4; mf++) {
        const int rg = row0 + warp_m * 64 + mf * 16 + g;
#pragma unroll
        for (int nf = 0; nf < 4; nf++) {
            const int cg = n0 + warp_n * 32 + nf * 8 + tg * 2;
            float2 v0 = make_float2(acc[mf][nf][0], acc[mf][nf][1]);
            float2 v1 = make_float2(acc[mf][nf][2], acc[mf][nf][3]);
            if (BIAS) {
                float b0v = biasScale * bias[cg], b1v = biasScale * bias[cg + 1];
                v0.x += b0v; v0.y += b1v; v1.x += b0v; v1.y += b1v;
            }
            *(float2*)(C + (size_t)rg * Hd + cg) = v0;
            *(float2*)(C + (size_t)(rg + 8) * Hd + cg) = v1;
        }
    }
}

__global__ __launch_bounds__(256, 2) void u_hmma_dyn_kernel() {
    hmma_gemm_body_dyn<false>(g_zh, g_zl, g_Mth, g_Mtl, g_u, nullptr, 0.f);
}
__global__ __launch_bounds__(256, 2) void x_hmma_dyn_kernel(const float* __restrict__ bv,
                                                            float* __restrict__ xout) {
    hmma_gemm_body_dyn<true>(g_yh, g_yl, g_Wvth, g_Wvtl, xout, bv, 4.f);
}

// ============================================================
// Fallback: R16-proven static-SMEM Kc=16 variant (48KB, 2 CTAs/SM)
// ============================================================
#define HK 16
#define HLD 24
#define SM_BUF (128 * HLD * 2)
#define SM_STG (4 * SM_BUF)
template <bool BIAS>
__device__ __forceinline__ void hmma_gemm_body_s(
    const __nv_bfloat16* __restrict__ Ah, const __nv_bfloat16* __restrict__ Al,
    const __nv_bfloat16* __restrict__ Bh, const __nv_bfloat16* __restrict__ Bl,
    float* __restrict__ C, const float* __restrict__ bias, float biasScale) {
    __shared__ __nv_bfloat16 sm[2][4][128][HLD];
    const int tid = threadIdx.x;
    const int wid = tid >> 5, lane = tid & 31;
    const int warp_m = wid & 1, warp_n = wid >> 1;
    const int g = lane >> 2, tg = lane & 3;
    const int row0 = blockIdx.y * 128, n0 = blockIdx.x * 128;
    const uint32_t sbase = smem_u32(sm);

    const __nv_bfloat16* ptr[4] = {Ah + (size_t)row0 * Hd, Al + (size_t)row0 * Hd,
                                   Bh + (size_t)n0 * Hd,  Bl + (size_t)n0 * Hd};
    const int lrow = tid >> 1, lq = tid & 1;
    const size_t goff = (size_t)lrow * Hd + lq * 8;
    const uint32_t soff = (uint32_t)(lrow * (HLD * 2) + lq * 16);
    auto cp_chunk = [&](int c, int s) {
        const size_t o = goff + (size_t)c * HK;
        const uint32_t d = sbase + s * SM_STG + soff;
#pragma unroll
        for (int b = 0; b < 4; b++) cp16(d + b * SM_BUF, ptr[b] + o);
    };
    const int arow = warp_m * 64 + g;
    const int brow = warp_n * 32 + g;
    const int kc = 2 * tg;
    float acc[4][4][4] = {};
    cp_chunk(0, 0);
    cp_commit();
    for (int c = 0; c < Hd / HK; c++) {
        const int s = c & 1;
        cp_wait<0>();
        __syncthreads();
        if (c < Hd / HK - 1) { cp_chunk(c + 1, s ^ 1); cp_commit(); }
        uint32_t ah[4][4], al[4][4], bh[4][2], bl[4][2];
#pragma unroll
        for (int mf = 0; mf < 4; mf++) {
            const int r = arow + mf * 16;
            ah[mf][0] = *(const uint32_t*)&sm[s][0][r][kc];
            ah[mf][1] = *(const uint32_t*)&sm[s][0][r + 8][kc];
            ah[mf][2] = *(const uint32_t*)&sm[s][0][r][kc + 8];
            ah[mf][3] = *(const uint32_t*)&sm[s][0][r + 8][kc + 8];
            al[mf][0] = *(const uint32_t*)&sm[s][1][r][kc];
            al[mf][1] = *(const uint32_t*)&sm[s][1][r + 8][kc];
            al[mf][2] = *(const uint32_t*)&sm[s][1][r][kc + 8];
            al[mf][3] = *(const uint32_t*)&sm[s][1][r + 8][kc + 8];
        }
#pragma unroll
        for (int nf = 0; nf < 4; nf++) {
            const int r = brow + nf * 8;
            bh[nf][0] = *(const uint32_t*)&sm[s][2][r][kc];
            bh[nf][1] = *(const uint32_t*)&sm[s][2][r][kc + 8];
            bl[nf][0] = *(const uint32_t*)&sm[s][3][r][kc];
            bl[nf][1] = *(const uint32_t*)&sm[s][3][r][kc + 8];
        }
#pragma unroll
        for (int mf = 0; mf < 4; mf++)
#pragma unroll
            for (int nf = 0; nf < 4; nf++)
                mma16816(acc[mf][nf], ah[mf], bh[nf][0], bh[nf][1]);
#pragma unroll
        for (int mf = 0; mf < 4; mf++)
#pragma unroll
            for (int nf = 0; nf < 4; nf++)
                mma16816(acc[mf][nf], al[mf], bh[nf][0], bh[nf][1]);
#pragma unroll
        for (int mf = 0; mf < 4; mf++)
#pragma unroll
            for (int nf = 0; nf < 4; nf++)
                mma16816(acc[mf][nf], ah[mf], bl[nf][0], bl[nf][1]);
        __syncthreads();
    }
#pragma unroll
    for (int mf = 0; mf < 4; mf++) {
        const int rg = row0 + warp_m * 64 + mf * 16 + g;
#pragma unroll
        for (int nf = 0; nf < 4; nf++) {
            const int cg = n0 + warp_n * 32 + nf * 8 + tg * 2;
            float2 v0 = make_float2(acc[mf][nf][0], acc[mf][nf][1]);
            float2 v1 = make_float2(acc[mf][nf][2], acc[mf][nf][3]);
            if (BIAS) {
                float b0v = biasScale * bias[cg], b1v = biasScale * bias[cg + 1];
                v0.x += b0v; v0.y += b1v; v1.x += b0v; v1.y += b1v;
            }
            *(float2*)(C + (size_t)rg * Hd + cg) = v0;
            *(float2*)(C + (size_t)(rg + 8) * Hd + cg) = v1;
        }
    }
}
__global__ __launch_bounds__(256, 2) void u_hmma_s_kernel() {
    hmma_gemm_body_s<false>(g_zh, g_zl, g_Mth, g_Mtl, g_u, nullptr, 0.f);
}
__global__ __launch_bounds__(256, 2) void x_hmma_s_kernel(const float* __restrict__ bv,
                                                          float* __restrict__ xout) {
    hmma_gemm_body_s<true>(g_yh, g_yl, g_Wvth, g_Wvtl, xout, bv, 4.f);
}

// ============================================================
// per-batch attention, register-resident (R12-proven)
// ============================================================
__global__ __launch_bounds__(128) void attn_kernel(const float* __restrict__ f1,
                                                   const float* __restrict__ f2,
                                                   const float* __restrict__ f3,
                                                   const float* __restrict__ f4) {
    const int b = blockIdx.x, tid = threadIdx.x;
    const int jb = tid * 8;

    float z[4][8], u[4][8];
#pragma unroll
    for (int t = 0; t < 4; t++) {
        const float4* zp = (const float4*)(fsel(f1, f2, f3, f4, t) + (size_t)b * Hd + jb);
        const float4* up = (const float4*)(g_u + ((size_t)b * 4 + t) * Hd + jb);
        *(float4*)&z[t][0] = zp[0]; *(float4*)&z[t][4] = zp[1];
        *(float4*)&u[t][0] = up[0]; *(float4*)&u[t][4] = up[1];
    }
    float vk8[8];
    *(float4*)&vk8[0] = *(const float4*)(g_vk + jb);
    *(float4*)&vk8[4] = *(const float4*)(g_vk + jb + 4);

    float aG[16] = {}, aC[4] = {};
#pragma unroll
    for (int j = 0; j < 8; j++) {
#pragma unroll
        for (int t = 0; t < 4; t++)
#pragma unroll
            for (int s = 0; s < 4; s++) aG[t * 4 + s] += u[t][j] * z[s][j];
#pragma unroll
        for (int s = 0; s < 4; s++) aC[s] += z[s][j] * vk8[j];
    }
#pragma unroll
    for (int a = 0; a < 16; a++)
#pragma unroll
        for (int off = 16; off; off >>= 1) aG[a] += __shfl_xor_sync(0xffffffffu, aG[a], off);
#pragma unroll
    for (int a = 0; a < 4; a++)
#pragma unroll
        for (int off = 16; off; off >>= 1) aC[a] += __shfl_xor_sync(0xffffffffu, aC[a], off);

    __shared__ float rbuf[4][20];
    __shared__ float sw[4];
    const int warp = tid >> 5, lane = tid & 31;
    if (lane == 0) {
#pragma unroll
        for (int a = 0; a < 16; a++) rbuf[warp][a] = aG[a];
#pragma unroll
        for (int a = 0; a < 4; a++) rbuf[warp][16 + a] = aC[a];
    }
    __syncthreads();
    if (tid == 0) {
        float L[20];
#pragma unroll
        for (int a = 0; a < 20; a++) L[a] = rbuf[0][a] + rbuf[1][a] + rbuf[2][a] + rbuf[3][a];
        float w[4] = {0.f, 0.f, 0.f, 0.f};
#pragma unroll
        for (int t = 0; t < 4; t++) {
            float l0 = L[t * 4 + 0] + L[16];
            float l1 = L[t * 4 + 1] + L[17];
            float l2 = L[t * 4 + 2] + L[18];
            float l3 = L[t * 4 + 3] + L[19];
            float m = fmaxf(fmaxf(l0, l1), fmaxf(l2, l3));
            float e0 = expf(l0 - m), e1 = expf(l1 - m), e2 = expf(l2 - m), e3 = expf(l3 - m);
            float inv = 1.f / (e0 + e1 + e2 + e3);
            w[0] += e0 * inv; w[1] += e1 * inv; w[2] += e2 * inv; w[3] += e3 * inv;
        }
        sw[0] = w[0]; sw[1] = w[1]; sw[2] = w[2]; sw[3] = w[3];
    }
    __syncthreads();
    const float w0 = sw[0], w1 = sw[1], w2 = sw[2], w3 = sw[3];

    __nv_bfloat162 oh[4], ol[4];
#pragma unroll
    for (int jj = 0; jj < 4; jj++) {
        float o0 = w0 * z[0][jj * 2]     + w1 * z[1][jj * 2]     + w2 * z[2][jj * 2]     + w3 * z[3][jj * 2];
        float o1 = w0 * z[0][jj * 2 + 1] + w1 * z[1][jj * 2 + 1] + w2 * z[2][jj * 2 + 1] + w3 * z[3][jj * 2 + 1];
        __nv_bfloat16 h0, l0, h1, l1;
        split_bf16(o0, h0, l0); split_bf16(o1, h1, l1);
        oh[jj] = __halves2bfloat162(h0, h1);
        ol[jj] = __halves2bfloat162(l0, l1);
    }
    *(uint2*)(g_yh + (size_t)b * Hd + jb)     = *(uint2*)&oh[0];
    *(uint2*)(g_yh + (size_t)b * Hd + jb + 4) = *(uint2*)&oh[2];
    *(uint2*)(g_yl + (size_t)b * Hd + jb)     = *(uint2*)&ol[0];
    *(uint2*)(g_yl + (size_t)b * Hd + jb + 4) = *(uint2*)&ol[2];
}

// ============================================================
// out = softmax(x @ Wfc + bfc)
// ============================================================
__global__ __launch_bounds__(128) void fc_kernel(const float* __restrict__ x,
                                                 const float* __restrict__ Wfc,
                                                 const float* __restrict__ bfc,
                                                 float* __restrict__ oout) {
    __shared__ float sxT[Hd][8];
    const int tid = threadIdx.x;
    const int row0 = blockIdx.x * 8;
    for (int idx = tid; idx < 8 * Hd; idx += 128) {
        int r = idx >> 10;
        int k = idx & (Hd - 1);
        sxT[k][r] = x[(size_t)(row0 + r) * Hd + k];
    }
    __syncthreads();
    float acc[8] = {};
#pragma unroll 4
    for (int k = 0; k < Hd; k++) {
        float wv = Wfc[(size_t)k * ODIM + tid];
        float4 lo = *(const float4*)&sxT[k][0];
        float4 hi = *(const float4*)&sxT[k][4];
        acc[0] += lo.x * wv; acc[1] += lo.y * wv; acc[2] += lo.z * wv; acc[3] += lo.w * wv;
        acc[4] += hi.x * wv; acc[5] += hi.y * wv; acc[6] += hi.z * wv; acc[7] += hi.w * wv;
    }
    const float bb = bfc[tid];
#pragma unroll
    for (int r = 0; r < 8; r++) acc[r] += bb;

    __shared__ float slog[8][128];
#pragma unroll
    for (int r = 0; r < 8; r++) slog[r][tid] = acc[r];
    __syncthreads();
    __shared__ float smax[8], sinv[8];
    const int warp = tid >> 5, lane = tid & 31;
#pragma unroll
    for (int rr = 0; rr < 2; rr++) {
        int r = warp * 2 + rr;
        float v0 = slog[r][lane], v1 = slog[r][lane + 32];
        float v2 = slog[r][lane + 64], v3 = slog[r][lane + 96];
        float m = fmaxf(fmaxf(v0, v1), fmaxf(v2, v3));
#pragma unroll
        for (int off = 16; off; off >>= 1) m = fmaxf(m, __shfl_xor_sync(0xffffffffu, m, off));
        float s = expf(v0 - m) + expf(v1 - m) + expf(v2 - m) + expf(v3 - m);
#pragma unroll
        for (int off = 16; off; off >>= 1) s += __shfl_xor_sync(0xffffffffu, s, off);
        if (lane == 0) { smax[r] = m; sinv[r] = 1.f / s; }
    }
    __syncthreads();
#pragma unroll
    for (int r = 0; r < 8; r++)
        oout[(size_t)(row0 + r) * ODIM + tid] = expf(acc[r] - smax[r]) * sinv[r];
}

// ============================================================
extern "C" void kernel_launch(void* const* d_in, const int* in_sizes, int n_in,
                              void* d_out, int out_size) {
    (void)in_sizes; (void)n_in; (void)out_size;
    const float* f1  = (const float*)d_in[0];
    const float* f2  = (const float*)d_in[1];
    const float* f3  = (const float*)d_in[2];
    const float* f4  = (const float*)d_in[3];
    const float* Wq  = (const float*)d_in[4];
    const float* bq  = (const float*)d_in[5];
    const float* Wk  = (const float*)d_in[6];
    // d_in[7] = bk: cancels inside softmax — unused
    const float* Wv  = (const float*)d_in[8];
    const float* bv  = (const float*)d_in[9];
    const float* Wfc = (const float*)d_in[10];
    const float* bfc = (const float*)d_in[11];

    float* xout = (float*)d_out;                 // [B, H]
    float* oout = xout + (size_t)Bsz * Hd;       // [B, OUT]

    // opt-in for the 80KB dynamic-SMEM GEMMs; fall back to static path on failure
    cudaError_t e1 = cudaFuncSetAttribute(
        u_hmma_dyn_kernel, cudaFuncAttributeMaxDynamicSharedMemorySize, SMEM_DYN);
    cudaError_t e2 = cudaFuncSetAttribute(
        x_hmma_dyn_kernel, cudaFuncAttributeMaxDynamicSharedMemorySize, SMEM_DYN);
    const bool use_dyn = (e1 == cudaSuccess && e2 == cudaSuccess);

    // bf16 split conversions + small precomputes
    prep_z_kernel<<<(RTOT * (Hd / 4)) / 256, 256>>>(f1, f2, f3, f4);
    mt_gemm_kernel<<<dim3(Hd / BN, Hd / BM), 256>>>(Wk, Wq);
    wvt_kernel<<<dim3(Hd / 32, Hd / 32), 256>>>(Wv);

    // u = z @ M  (HMMA bf16x3) — 4th launch: ncu profiles this
    if (use_dyn)
        u_hmma_dyn_kernel<<<dim3(Hd / 128, RTOT / 128), 256, SMEM_DYN>>>();
    else
        u_hmma_s_kernel<<<dim3(Hd / 128, RTOT / 128), 256>>>();

    // vk needed only by attn
    vk_kernel<<<Hd / 8, 256>>>(Wk, bq);

    // attention reduce -> y (bf16 split, register-resident)
    attn_kernel<<<Bsz, 128>>>(f1, f2, f3, f4);

    // x = y @ Wv + 4*bv  (HMMA bf16x3)
    if (use_dyn)
        x_hmma_dyn_kernel<<<dim3(Hd / 128, Bsz / 128), 256, SMEM_DYN>>>(bv, xout);
    else
        x_hmma_s_kernel<<<dim3(Hd / 128, Bsz / 128), 256>>>(bv, xout);

    // out = softmax(x @ Wfc + bfc)
    fc_kernel<<<Bsz / 8, 128>>>(xout, Wfc, bfc, oout);
}